// round 13
// baseline (speedup 1.0000x reference)
#include <cuda_runtime.h>
#include <cuda_bf16.h>
#include <cuda_fp16.h>
#include <math.h>
#include <stdint.h>

#define BZ    64
#define CINC  96
#define COUTC 96
#define MIDC  192
#define HWP   3136
#define EPSBN 1e-5f

#define BSS 136                    // pair-row stride (u32): bank = 8*tg+g, conflict-free
#define EXP_A_U32   6144           // per-mt A chunk  [wr2][ki6][mi2][hl2][lane32][q4]
#define PROJ_A_U32  4608           // per-kchunk A    [wr2][ki3][mi3][hl2][lane32][q4]
#define EXP_B_U32   (48 * BSS)     // one plane (hi or lo), 48 pair-rows
#define PROJ_B_U32  (24 * BSS)     // one plane per chunk, 24 pair-rows
#define EXP_SMEM  ((2 * EXP_A_U32 + 2 * EXP_B_U32) * 4)      // 101376 B
#define PROJ_SMEM ((2 * PROJ_A_U32 + 4 * PROJ_B_U32) * 4)    // 89088 B

// Scratch (device globals: allowed; no cudaMalloc anywhere)
__device__ __align__(16) __half   g_mid[(size_t)BZ * MIDC * HWP];    // fp16 mid
__device__ __align__(16) uint32_t g_mergedH[(size_t)BZ * 96 * HWP];  // packed bf16 (c,c+1) hi
__device__ __align__(16) uint32_t g_mergedL[(size_t)BZ * 96 * HWP];  // packed bf16 lo residual
__device__ float    g_sums[BZ * MIDC];
__device__ __align__(16) uint32_t g_WexpF[18432];   // [mt3][wr2][ki6][mi2][hl2][lane32][q4]
__device__ __align__(16) uint32_t g_WprojF[18432];  // [chunk4][wr2][ki3][mi3][hl2][lane32][q4]
__device__ __align__(16) uint32_t g_WprojSE[(size_t)BZ * 18432];  // per-batch SE-scaled resplit
__device__ float    g_bexp[MIDC];
__device__ float    g_W9[MIDC * 9];
__device__ float    g_T[MIDC];
__device__ float    g_bproj[COUTC];

__device__ __forceinline__ float silu_f(float v) { return v / (1.f + __expf(-v)); }

__device__ __forceinline__ uint32_t packbf2(float lo_elem, float hi_elem) {
    __nv_bfloat162 t = __floats2bfloat162_rn(lo_elem, hi_elem);  // .x = low 16 bits
    return *(uint32_t*)&t;
}
__device__ __forceinline__ float2 unpackbf2(uint32_t u) {
    __nv_bfloat162 t = *(__nv_bfloat162*)&u;
    return __bfloat1622float2(t);
}
__device__ __forceinline__ float bf16hi(float v) {
    return __bfloat162float(__float2bfloat16_rn(v));
}

__device__ __forceinline__ void mma16(float* c, const uint32_t* a, const uint32_t* b) {
    asm volatile(
        "mma.sync.aligned.m16n8k16.row.col.f32.bf16.bf16.f32 "
        "{%0,%1,%2,%3},{%4,%5,%6,%7},{%8,%9},{%0,%1,%2,%3};"
        : "+f"(c[0]), "+f"(c[1]), "+f"(c[2]), "+f"(c[3])
        : "r"(a[0]), "r"(a[1]), "r"(a[2]), "r"(a[3]), "r"(b[0]), "r"(b[1]));
}

__device__ __forceinline__ uint32_t smaddr(const void* p) {
    return (uint32_t)__cvta_generic_to_shared(p);
}
__device__ __forceinline__ void cpa16(uint32_t dst_s, const void* src, bool valid) {
    // NOTE: valid=false still WRITES 16 zero bytes to dst (zero-fill), use only
    // where zero-padding the destination is intended.
    int sz = valid ? 16 : 0;
    asm volatile("cp.async.cg.shared.global [%0], [%1], 16, %2;\n"
                 :: "r"(dst_s), "l"(src), "r"(sz));
}
__device__ __forceinline__ void cpa_commit() {
    asm volatile("cp.async.commit_group;\n");
}
template <int N>
__device__ __forceinline__ void cpa_wait() {
    asm volatile("cp.async.wait_group %0;\n" :: "n"(N));
}

// ---------------------------------------------------------------------------
// prep: fold BN; emit fragment-ordered packed-bf16 hi/lo weights.
// ---------------------------------------------------------------------------
__global__ void prep_kernel(const float* __restrict__ expand_w,
                            const float* __restrict__ expand_bn,
                            const float* __restrict__ dw_w,
                            const float* __restrict__ dw_bn,
                            const float* __restrict__ id_w,
                            const float* __restrict__ id_bn,
                            const float* __restrict__ merge_bn,
                            const float* __restrict__ proj_w,
                            const float* __restrict__ proj_bn) {
    int tid = blockIdx.x * blockDim.x + threadIdx.x;
    int nth = gridDim.x * blockDim.x;

    for (int idx = tid; idx < 18432; idx += nth) {
        int q = idx & 3, lane = (idx >> 2) & 31, hl = (idx >> 7) & 1;
        int t = idx >> 8;
        int mi = t & 1; t >>= 1;
        int ki = t % 6; t /= 6;
        int wr = t & 1; t >>= 1;
        int mt = t;
        int m = mt * 64 + wr * 32 + mi * 16 + (lane >> 2) + 8 * (q & 1);
        int k = ki * 16 + (lane & 3) * 2 + 8 * (q >> 1);
        float sc = expand_bn[m] * rsqrtf(expand_bn[3 * MIDC + m] + EPSBN);
        float w0 = expand_w[m * CINC + k] * sc;
        float w1 = expand_w[m * CINC + k + 1] * sc;
        float h0 = bf16hi(w0), h1 = bf16hi(w1);
        g_WexpF[idx] = hl ? packbf2(w0 - h0, w1 - h1) : packbf2(h0, h1);
    }
    for (int idx = tid; idx < 18432; idx += nth) {
        int q = idx & 3, lane = (idx >> 2) & 31, hl = (idx >> 7) & 1;
        int t = idx >> 8;
        int mi = t % 3; t /= 3;
        int ki = t % 3; t /= 3;
        int wr = t & 1; int chunk = t >> 1;
        int m = wr * 48 + mi * 16 + (lane >> 2) + 8 * (q & 1);
        int k = chunk * 48 + ki * 16 + (lane & 3) * 2 + 8 * (q >> 1);
        float sc = proj_bn[m] * rsqrtf(proj_bn[3 * COUTC + m] + EPSBN);
        float w0 = proj_w[m * MIDC + k] * sc;
        float w1 = proj_w[m * MIDC + k + 1] * sc;
        float h0 = bf16hi(w0), h1 = bf16hi(w1);
        g_WprojF[idx] = hl ? packbf2(w0 - h0, w1 - h1) : packbf2(h0, h1);
    }
    for (int o = tid; o < MIDC; o += nth) {
        float sc = expand_bn[o] * rsqrtf(expand_bn[3 * MIDC + o] + EPSBN);
        g_bexp[o] = expand_bn[MIDC + o] - expand_bn[2 * MIDC + o] * sc;
    }
    for (int c = tid; c < MIDC; c += nth) {
        float dsc = dw_bn[c] * rsqrtf(dw_bn[3 * MIDC + c] + EPSBN);
        float dsh = dw_bn[MIDC + c] - dw_bn[2 * MIDC + c] * dsc;
        float isc = id_bn[c] * rsqrtf(id_bn[3 * MIDC + c] + EPSBN);
        float ish = id_bn[MIDC + c] - id_bn[2 * MIDC + c] * isc;
        float msc = merge_bn[c] * rsqrtf(merge_bn[3 * MIDC + c] + EPSBN);
        float msh = merge_bn[MIDC + c] - merge_bn[2 * MIDC + c] * msc;
        #pragma unroll
        for (int k = 0; k < 9; k++) g_W9[c * 9 + k] = msc * dsc * dw_w[c * 9 + k];
        g_W9[c * 9 + 4] += msc * isc * id_w[c];
        g_T[c] = msc * (dsh + ish) + msh;
    }
    for (int o = tid; o < COUTC; o += nth) {
        float sc = proj_bn[o] * rsqrtf(proj_bn[3 * COUTC + o] + EPSBN);
        g_bproj[o] = proj_bn[COUTC + o] - proj_bn[2 * COUTC + o] * sc;
    }
}

// ---------------------------------------------------------------------------
// Expand 1x1 GEMM. 192(Mx3 passes) x 128(N); warp tile 32x32; bf16 k16.
// A depth-2 cp.async pipeline; B converted once at start. fp16 output.
// ---------------------------------------------------------------------------
__global__ void __launch_bounds__(256, 2) expand_gemm(const float* __restrict__ x) {
    extern __shared__ uint32_t smu[];
    uint32_t* As0 = smu;                    // EXP_A_U32
    uint32_t* As1 = smu + EXP_A_U32;
    uint32_t* Bh  = smu + 2 * EXP_A_U32;    // EXP_B_U32
    uint32_t* Bl  = Bh + EXP_B_U32;
    int b = blockIdx.z;
    int p0 = blockIdx.x * 128;
    int tid = threadIdx.x;
    int lane = tid & 31, w = tid >> 5;
    int wr = w >> 2, wc = w & 3;
    int g = lane >> 2, tg = lane & 3;
    const float* xb = x + (size_t)b * CINC * HWP;
    __half* ob = g_mid + (size_t)b * MIDC * HWP;

    // Prefetch A(0) and A(1) upfront (two commit groups)
    {
        const uint4* src = (const uint4*)g_WexpF;
        #pragma unroll
        for (int j = 0; j < 6; j++)
            cpa16(smaddr(As0) + (tid + j * 256) * 16, src + tid + j * 256, true);
        cpa_commit();
        src += EXP_A_U32 / 4;
        #pragma unroll
        for (int j = 0; j < 6; j++)
            cpa16(smaddr(As1) + (tid + j * 256) * 16, src + tid + j * 256, true);
        cpa_commit();
    }
    // Convert B (overlaps both A fetches)
    #pragma unroll
    for (int j = 0; j < 6; j++) {
        int v = tid + j * 256;
        int k2 = v >> 5, c4 = (v & 31) << 2;
        int p = p0 + c4;
        float4 r0 = make_float4(0.f, 0.f, 0.f, 0.f), r1 = r0;
        if (p < HWP) {
            r0 = *(const float4*)&xb[(size_t)(2 * k2) * HWP + p];
            r1 = *(const float4*)&xb[(size_t)(2 * k2 + 1) * HWP + p];
        }
        float e0[4] = {r0.x, r0.y, r0.z, r0.w};
        float e1[4] = {r1.x, r1.y, r1.z, r1.w};
        uint32_t hh[4], ll[4];
        #pragma unroll
        for (int i = 0; i < 4; i++) {
            float h0 = bf16hi(e0[i]), h1 = bf16hi(e1[i]);
            hh[i] = packbf2(h0, h1);
            ll[i] = packbf2(e0[i] - h0, e1[i] - h1);
        }
        *(uint4*)&Bh[k2 * BSS + c4] = make_uint4(hh[0], hh[1], hh[2], hh[3]);
        *(uint4*)&Bl[k2 * BSS + c4] = make_uint4(ll[0], ll[1], ll[2], ll[3]);
    }

    for (int mt = 0; mt < 3; mt++) {
        uint32_t* Acur = (mt & 1) ? As1 : As0;
        if (mt == 2) { cpa_wait<0>(); } else { cpa_wait<1>(); }
        __syncthreads();   // A(mt) visible; B visible (mt=0); prev buffer free

        float acc[2][4][4] = {};
        #pragma unroll
        for (int ki = 0; ki < 6; ki++) {
            uint4 ah[2], al[2];
            #pragma unroll
            for (int mi = 0; mi < 2; mi++) {
                int off = (((wr * 6 + ki) * 2 + mi) * 2) * 128 + lane * 4;
                ah[mi] = *(const uint4*)&Acur[off];
                al[mi] = *(const uint4*)&Acur[off + 128];
            }
            uint32_t bh[4][2], bl[4][2];
            int kr2 = ki * 8;
            #pragma unroll
            for (int ni = 0; ni < 4; ni++) {
                int nb = wc * 32 + ni * 8 + g;
                bh[ni][0] = Bh[(kr2 + tg) * BSS + nb];
                bh[ni][1] = Bh[(kr2 + tg + 4) * BSS + nb];
                bl[ni][0] = Bl[(kr2 + tg) * BSS + nb];
                bl[ni][1] = Bl[(kr2 + tg + 4) * BSS + nb];
            }
            #pragma unroll
            for (int mi = 0; mi < 2; mi++)
                #pragma unroll
                for (int ni = 0; ni < 4; ni++) {
                    mma16(acc[mi][ni], (const uint32_t*)&ah[mi], bh[ni]);
                    mma16(acc[mi][ni], (const uint32_t*)&al[mi], bh[ni]);
                    mma16(acc[mi][ni], (const uint32_t*)&ah[mi], bl[ni]);
                }
        }

        int m0 = mt * 64;
        #pragma unroll
        for (int mi = 0; mi < 2; mi++) {
            int o = m0 + wr * 32 + mi * 16 + g;
            float b0f = g_bexp[o], b1f = g_bexp[o + 8];
            #pragma unroll
            for (int ni = 0; ni < 4; ni++) {
                int p = p0 + wc * 32 + ni * 8 + tg * 2;
                if (p < HWP) {
                    *(__half2*)&ob[(size_t)o * HWP + p] =
                        __floats2half2_rn(silu_f(acc[mi][ni][0] + b0f),
                                          silu_f(acc[mi][ni][1] + b0f));
                    *(__half2*)&ob[(size_t)(o + 8) * HWP + p] =
                        __floats2half2_rn(silu_f(acc[mi][ni][2] + b1f),
                                          silu_f(acc[mi][ni][3] + b1f));
                }
            }
        }
        __syncthreads();   // all reads of Acur done before refill
        if (mt == 0) {
            const uint4* src = ((const uint4*)g_WexpF) + 2 * (EXP_A_U32 / 4);
            #pragma unroll
            for (int j = 0; j < 6; j++)
                cpa16(smaddr(As0) + (tid + j * 256) * 16, src + tid + j * 256, true);
            cpa_commit();
        }
    }
}

// ---------------------------------------------------------------------------
// dwmerge v2: vectorized; shifted planes at col offset OFF=5-ox. fp16 input.
// ---------------------------------------------------------------------------
#define SROW 64
__global__ void __launch_bounds__(256) dwmerge_kernel() {
    __shared__ float sps[2][58 * SROW];
    __shared__ float sred[16];
    int bc = blockIdx.x;
    int b = bc / 96, k2 = bc - b * 96;
    int tid = threadIdx.x;

    int oyA[2], oxA[2];
    const __half* planes[2];
    float w9[2][9], T[2];
    #pragma unroll
    for (int ch = 0; ch < 2; ch++) {
        int c = 2 * k2 + ch;
        int cpre = (c & 3) * 48 + (c >> 2);
        int gg = c & 3;
        oyA[ch] = (gg == 0) ? -1 : (gg == 2) ? 1 : 0;
        oxA[ch] = (gg == 1) ? -1 : (gg == 3) ? 1 : 0;
        planes[ch] = g_mid + ((size_t)b * MIDC + cpre) * HWP;
        #pragma unroll
        for (int k = 0; k < 9; k++) w9[ch][k] = g_W9[c * 9 + k];
        T[ch] = g_T[c];
    }

    // Pass 1: zero both planes (float4)
    {
        float4* z = (float4*)&sps[0][0];
        for (int i = tid; i < 2 * 58 * SROW / 4; i += 256)
            z[i] = make_float4(0.f, 0.f, 0.f, 0.f);
    }
    __syncthreads();

    // Pass 2: fill valid rows; fp16 loads (8B-aligned: row stride 112B, qq*8B)
    for (int t = tid; t < 1624; t += 256) {
        int ch = t >= 812;
        int u = t - ch * 812;
        int r = u / 14, qq = u - r * 14;
        int hp = r - 1, hs = hp + oyA[ch];
        if ((unsigned)hp < 56u && (unsigned)hs < 56u) {
            uint2 v = *(const uint2*)&planes[ch][hs * 56 + qq * 4];
            float2 f01 = __half22float2(*(__half2*)&v.x);
            float2 f23 = __half22float2(*(__half2*)&v.y);
            float* d = &sps[ch][r * SROW + qq * 4 + (5 - oxA[ch])];
            d[0] = f01.x; d[1] = f01.y; d[2] = f23.x; d[3] = f23.y;
        }
    }
    __syncthreads();

    // Pass 3: zero the conv-pad cell that the shifted copy filled
    if (tid < 116) {
        int ch = tid >= 58;
        int r = tid - ch * 58;
        int ox = oxA[ch];
        if (ox == 1)  sps[ch][r * SROW + 4] = 0.f;   // wp=-1 cell
        if (ox == -1) sps[ch][r * SROW + 61] = 0.f;  // wp=56 cell
    }
    __syncthreads();

    uint32_t* oH = g_mergedH + ((size_t)b * 96 + k2) * HWP;
    uint32_t* oL = g_mergedL + ((size_t)b * 96 + k2) * HWP;
    float ls0 = 0.f, ls1 = 0.f;

    for (int t = tid; t < 784; t += 256) {
        int h = t / 14, q = t - h * 14;
        float a0[4] = {T[0], T[0], T[0], T[0]};
        float a1[4] = {T[1], T[1], T[1], T[1]};
        #pragma unroll
        for (int ch = 0; ch < 2; ch++) {
            float* accp = ch ? a1 : a0;
            #pragma unroll
            for (int dy = 0; dy < 3; dy++) {
                const float* row = &sps[ch][(h + dy) * SROW + q * 4 + 4];
                float4 A = *(const float4*)row;
                float2 Bv = *(const float2*)(row + 4);
                float wA = w9[ch][dy * 3], wB = w9[ch][dy * 3 + 1], wC = w9[ch][dy * 3 + 2];
                accp[0] += wA * A.x + wB * A.y + wC * A.z;
                accp[1] += wA * A.y + wB * A.z + wC * A.w;
                accp[2] += wA * A.z + wB * A.w + wC * Bv.x;
                accp[3] += wA * A.w + wB * Bv.x + wC * Bv.y;
            }
        }
        uint32_t Hw[4], Lw[4];
        #pragma unroll
        for (int i = 0; i < 4; i++) {
            float s0 = silu_f(a0[i]);
            float s1 = silu_f(a1[i]);
            float h0 = bf16hi(s0), h1 = bf16hi(s1);
            Hw[i] = packbf2(h0, h1);
            Lw[i] = packbf2(s0 - h0, s1 - h1);
            ls0 += s0;
            ls1 += s1;
        }
        int o = h * 56 + q * 4;
        *(uint4*)&oH[o] = make_uint4(Hw[0], Hw[1], Hw[2], Hw[3]);
        *(uint4*)&oL[o] = make_uint4(Lw[0], Lw[1], Lw[2], Lw[3]);
    }

    int wid = tid >> 5, lane = tid & 31;
    #pragma unroll
    for (int o = 16; o > 0; o >>= 1) {
        ls0 += __shfl_down_sync(0xffffffffu, ls0, o);
        ls1 += __shfl_down_sync(0xffffffffu, ls1, o);
    }
    if (lane == 0) { sred[wid] = ls0; sred[8 + wid] = ls1; }
    __syncthreads();
    if (tid < 16) {
        float v = sred[tid];
        #pragma unroll
        for (int o = 4; o > 0; o >>= 1) v += __shfl_down_sync(0xffffu, v, o);
        if (tid == 0) g_sums[b * 192 + 2 * k2] = v;
        if (tid == 8) g_sums[b * 192 + 2 * k2 + 1] = v;
    }
}

// ---------------------------------------------------------------------------
// SE gating + per-batch scaled/resplit proj weights. Block = (batch, chunk).
// ---------------------------------------------------------------------------
__global__ void __launch_bounds__(256) se_scale_kernel(const float* __restrict__ red_w,
                                                       const float* __restrict__ red_b,
                                                       const float* __restrict__ exp_w,
                                                       const float* __restrict__ exp_b) {
    __shared__ float smean[192];
    __shared__ float sredu[24];
    __shared__ float s_se[192];
    int b = blockIdx.x, cc = blockIdx.y;
    int tid = threadIdx.x;

    if (tid < 192) smean[tid] = g_sums[b * 192 + tid] * (1.f / 3136.f);
    __syncthreads();
    if (tid < 24) {
        int gq = tid >> 1;
        float a = red_b[tid];
        #pragma unroll
        for (int i = 0; i < 16; i++) a += red_w[tid * 16 + i] * smean[gq * 16 + i];
        sredu[tid] = fmaxf(a, 0.f);
    }
    __syncthreads();
    if (tid < 192) {
        int gq = tid >> 4;
        float v = exp_w[tid * 2] * sredu[gq * 2] + exp_w[tid * 2 + 1] * sredu[gq * 2 + 1]
                + exp_b[tid];
        s_se[tid] = 1.f / (1.f + __expf(-v));
    }
    __syncthreads();

    uint32_t* dstb = g_WprojSE + (size_t)b * 18432;
    const uint4* src = ((const uint4*)g_WprojF) + cc * (PROJ_A_U32 / 4);
    uint4* dst = ((uint4*)dstb) + cc * (PROJ_A_U32 / 4);
    for (int i = tid; i < 576; i += 256) {
        int grp = i >> 5, li = i & 31;
        int ki = (grp / 3) % 3;
        uint4 H = src[grp * 64 + li];
        uint4 L = src[grp * 64 + li + 32];
        int k2a = cc * 24 + ki * 8 + (li & 3);
        float se0 = s_se[2 * k2a], se1 = s_se[2 * k2a + 1];
        float se2 = s_se[2 * k2a + 8], se3 = s_se[2 * k2a + 9];
        uint32_t hu[4] = {H.x, H.y, H.z, H.w};
        uint32_t lu[4] = {L.x, L.y, L.z, L.w};
        uint32_t nh[4], nl[4];
        #pragma unroll
        for (int q = 0; q < 4; q++) {
            float sA = (q < 2) ? se0 : se2;
            float sB = (q < 2) ? se1 : se3;
            float2 hf = unpackbf2(hu[q]);
            float2 lf = unpackbf2(lu[q]);
            float v0 = (hf.x + lf.x) * sA;
            float v1 = (hf.y + lf.y) * sB;
            float h0 = bf16hi(v0), h1 = bf16hi(v1);
            nh[q] = packbf2(h0, h1);
            nl[q] = packbf2(v0 - h0, v1 - h1);
        }
        dst[grp * 64 + li]      = make_uint4(nh[0], nh[1], nh[2], nh[3]);
        dst[grp * 64 + li + 32] = make_uint4(nl[0], nl[1], nl[2], nl[3]);
    }
}

// ---------------------------------------------------------------------------
// Project 1x1 GEMM — PERSISTENT. Grid = 320 blocks; each owns 5 (b, tile)
// items; depth-2 cp.async pipeline threaded ACROSS item boundaries so the
// pipeline never drains between tiles. Epilogue = plain LDG residual.
// ---------------------------------------------------------------------------
#define PROJ_ITEMS 5
__global__ void __launch_bounds__(256, 2) proj_gemm(const float* __restrict__ x,
                                                    float* __restrict__ out) {
    extern __shared__ uint32_t smu[];
    uint32_t* As0 = smu;                        // PROJ_A_U32
    uint32_t* As1 = smu + PROJ_A_U32;
    uint32_t* Bst = smu + 2 * PROJ_A_U32;       // 2 stages x 2 planes x PROJ_B_U32

    int item0 = blockIdx.x * PROJ_ITEMS;
    int tid = threadIdx.x;
    int lane = tid & 31, w = tid >> 5;
    int wr = w >> 2, wc = w & 3;
    int g = lane >> 2, tg = lane & 3;

    auto cp_stage_g = [&](int gg) {
        int stage = gg & 1;
        int item = item0 + (gg >> 2);
        int c = gg & 3;
        int b = item / 25;
        int p0 = (item - b * 25) * 128;
        const uint32_t* mH = g_mergedH + (size_t)b * 96 * HWP;
        const uint32_t* mL = g_mergedL + (size_t)b * 96 * HWP;
        uint32_t dstB = smaddr(Bst) + stage * 2 * PROJ_B_U32 * 4;
        const uint4* sH = (const uint4*)(mH + (size_t)(c * 24) * HWP);
        const uint4* sL = (const uint4*)(mL + (size_t)(c * 24) * HWP);
        #pragma unroll
        for (int j = 0; j < 3; j++) {
            int v = tid + j * 256;
            int r = v >> 5, c4 = (v & 31);
            int p = p0 + c4 * 4;
            bool ok = p < HWP;                  // zero-fill pad (intended)
            size_t so = (size_t)r * (HWP / 4) + (p0 >> 2) + c4;
            uint32_t d = dstB + (r * BSS + c4 * 4) * 4;
            cpa16(d, sH + (ok ? so : 0), ok);
            cpa16(d + PROJ_B_U32 * 4, sL + (ok ? so : 0), ok);
        }
        // A chunk: 1152 uint4 = 4*256 + 128 exact
        uint32_t dstA = smaddr(stage ? As1 : As0);
        const uint4* sA = ((const uint4*)(g_WprojSE + (size_t)b * 18432))
                          + c * (PROJ_A_U32 / 4);
        #pragma unroll
        for (int j = 0; j < 4; j++) {
            int v = tid + j * 256;
            cpa16(dstA + v * 16, sA + v, true);
        }
        if (tid < 128) {
            int v = tid + 1024;
            cpa16(dstA + v * 16, sA + v, true);
        }
        cpa_commit();
    };
    cp_stage_g(0);
    cp_stage_g(1);

    float acc[3][4][4] = {};
    const int TOT = PROJ_ITEMS * 4;

    for (int gg = 0; gg < TOT; gg++) {
        uint32_t* Acur = (gg & 1) ? As1 : As0;
        uint32_t* BhS = Bst + (gg & 1) * 2 * PROJ_B_U32;
        uint32_t* BlS = BhS + PROJ_B_U32;
        if (gg == TOT - 1) { cpa_wait<0>(); } else { cpa_wait<1>(); }
        __syncthreads();

        #pragma unroll
        for (int ki = 0; ki < 3; ki++) {
            uint4 ah[3], al[3];
            #pragma unroll
            for (int mi = 0; mi < 3; mi++) {
                int off = ((wr * 3 + ki) * 3 + mi) * 256 + lane * 4;
                ah[mi] = *(const uint4*)&Acur[off];
                al[mi] = *(const uint4*)&Acur[off + 128];
            }
            uint32_t bh[4][2], bl[4][2];
            int kr2 = ki * 8;
            #pragma unroll
            for (int ni = 0; ni < 4; ni++) {
                int nb = wc * 32 + ni * 8 + g;
                bh[ni][0] = BhS[(kr2 + tg) * BSS + nb];
                bh[ni][1] = BhS[(kr2 + tg + 4) * BSS + nb];
                bl[ni][0] = BlS[(kr2 + tg) * BSS + nb];
                bl[ni][1] = BlS[(kr2 + tg + 4) * BSS + nb];
            }
            #pragma unroll
            for (int mi = 0; mi < 3; mi++)
                #pragma unroll
                for (int ni = 0; ni < 4; ni++) {
                    mma16(acc[mi][ni], (const uint32_t*)&ah[mi], bh[ni]);
                    mma16(acc[mi][ni], (const uint32_t*)&al[mi], bh[ni]);
                    mma16(acc[mi][ni], (const uint32_t*)&ah[mi], bl[ni]);
                }
        }
        __syncthreads();      // buffer (gg&1) now free for refill

        if (gg + 2 < TOT) cp_stage_g(gg + 2);

        if ((gg & 3) == 3) {
            // Item epilogue: registers + gmem only (overlaps in-flight copies)
            int item = item0 + (gg >> 2);
            int b = item / 25;
            int p0 = (item - b * 25) * 128;
            const float* xb = x + (size_t)b * COUTC * HWP;
            float* ob = out + (size_t)b * COUTC * HWP;
            #pragma unroll
            for (int mi = 0; mi < 3; mi++) {
                int o = wr * 48 + mi * 16 + g;
                float b0f = g_bproj[o], b1f = g_bproj[o + 8];
                #pragma unroll
                for (int ni = 0; ni < 4; ni++) {
                    int p = p0 + wc * 32 + ni * 8 + tg * 2;
                    if (p < HWP) {
                        float2 x0 = *(const float2*)&xb[(size_t)o * HWP + p];
                        float2 r0;
                        r0.x = silu_f(acc[mi][ni][0] + b0f + x0.x);
                        r0.y = silu_f(acc[mi][ni][1] + b0f + x0.y);
                        *(float2*)&ob[(size_t)o * HWP + p] = r0;
                        float2 x1 = *(const float2*)&xb[(size_t)(o + 8) * HWP + p];
                        float2 r1;
                        r1.x = silu_f(acc[mi][ni][2] + b1f + x1.x);
                        r1.y = silu_f(acc[mi][ni][3] + b1f + x1.y);
                        *(float2*)&ob[(size_t)(o + 8) * HWP + p] = r1;
                    }
                }
            }
            #pragma unroll
            for (int mi = 0; mi < 3; mi++)
                #pragma unroll
                for (int ni = 0; ni < 4; ni++)
                    #pragma unroll
                    for (int q = 0; q < 4; q++)
                        acc[mi][ni][q] = 0.f;
        }
    }
}

// ---------------------------------------------------------------------------
extern "C" void kernel_launch(void* const* d_in, const int* in_sizes, int n_in,
                              void* d_out, int out_size) {
    const float* x         = (const float*)d_in[0];
    const float* expand_w  = (const float*)d_in[1];
    const float* expand_bn = (const float*)d_in[2];
    const float* dw_w      = (const float*)d_in[3];
    const float* dw_bn     = (const float*)d_in[4];
    const float* id_w      = (const float*)d_in[5];
    const float* id_bn     = (const float*)d_in[6];
    const float* merge_bn  = (const float*)d_in[7];
    const float* se_red_w  = (const float*)d_in[8];
    const float* se_red_b  = (const float*)d_in[9];
    const float* se_exp_w  = (const float*)d_in[10];
    const float* se_exp_b  = (const float*)d_in[11];
    const float* proj_w    = (const float*)d_in[12];
    const float* proj_bn   = (const float*)d_in[13];
    float* out = (float*)d_out;

    cudaFuncSetAttribute(expand_gemm, cudaFuncAttributeMaxDynamicSharedMemorySize, EXP_SMEM);
    cudaFuncSetAttribute(proj_gemm,   cudaFuncAttributeMaxDynamicSharedMemorySize, PROJ_SMEM);

    prep_kernel<<<264, 256>>>(expand_w, expand_bn, dw_w, dw_bn, id_w, id_bn,
                              merge_bn, proj_w, proj_bn);
    expand_gemm<<<dim3(25, 1, BZ), 256, EXP_SMEM>>>(x);
    dwmerge_kernel<<<BZ * 96, 256>>>();
    se_scale_kernel<<<dim3(BZ, 4), 256>>>(se_red_w, se_red_b, se_exp_w, se_exp_b);
    proj_gemm<<<320, 256, PROJ_SMEM>>>(x, out);
}

// round 14
// speedup vs baseline: 1.3068x; 1.3068x over previous
#include <cuda_runtime.h>
#include <cuda_bf16.h>
#include <cuda_fp16.h>
#include <math.h>
#include <stdint.h>

#define BZ    64
#define CINC  96
#define COUTC 96
#define MIDC  192
#define HWP   3136
#define EPSBN 1e-5f

#define BSS 136                    // pair-row stride (u32): bank = 8*tg+g, conflict-free
#define EXP_A_U32   6144           // per-mt A chunk  [wr2][ki6][mi2][hl2][lane32][q4]
#define PROJ_A_U32  4608           // per-kchunk A    [wr2][ki3][mi3][hl2][lane32][q4]
#define EXP_B_U32   (48 * BSS)     // one plane (hi or lo), 48 pair-rows
#define PROJ_B_U32  (24 * BSS)     // one plane per chunk, 24 pair-rows
#define EXP_SMEM  ((2 * EXP_A_U32 + 2 * EXP_B_U32) * 4)      // 101376 B
#define PROJ_SMEM ((2 * PROJ_A_U32 + 4 * PROJ_B_U32) * 4)    // 89088 B

// Scratch (device globals: allowed; no cudaMalloc anywhere)
__device__ __align__(16) __half   g_mid[(size_t)BZ * MIDC * HWP];    // fp16 mid
__device__ __align__(16) uint32_t g_mergedH[(size_t)BZ * 96 * HWP];  // packed bf16 (c,c+1) hi
__device__ __align__(16) uint32_t g_mergedL[(size_t)BZ * 96 * HWP];  // packed bf16 lo residual
__device__ float    g_sums[BZ * MIDC];
__device__ __align__(16) uint32_t g_WexpF[18432];   // [mt3][wr2][ki6][mi2][hl2][lane32][q4]
__device__ __align__(16) uint32_t g_WprojF[18432];  // [chunk4][wr2][ki3][mi3][hl2][lane32][q4]
__device__ __align__(16) uint32_t g_WprojSE[(size_t)BZ * 18432];  // per-batch SE-scaled resplit
__device__ float    g_bexp[MIDC];
__device__ float    g_W9[MIDC * 9];
__device__ float    g_T[MIDC];
__device__ float    g_bproj[COUTC];

__device__ __forceinline__ float silu_f(float v) { return v / (1.f + __expf(-v)); }

__device__ __forceinline__ uint32_t packbf2(float lo_elem, float hi_elem) {
    __nv_bfloat162 t = __floats2bfloat162_rn(lo_elem, hi_elem);  // .x = low 16 bits
    return *(uint32_t*)&t;
}
__device__ __forceinline__ float2 unpackbf2(uint32_t u) {
    __nv_bfloat162 t = *(__nv_bfloat162*)&u;
    return __bfloat1622float2(t);
}
__device__ __forceinline__ float bf16hi(float v) {
    return __bfloat162float(__float2bfloat16_rn(v));
}

__device__ __forceinline__ void mma16(float* c, const uint32_t* a, const uint32_t* b) {
    asm volatile(
        "mma.sync.aligned.m16n8k16.row.col.f32.bf16.bf16.f32 "
        "{%0,%1,%2,%3},{%4,%5,%6,%7},{%8,%9},{%0,%1,%2,%3};"
        : "+f"(c[0]), "+f"(c[1]), "+f"(c[2]), "+f"(c[3])
        : "r"(a[0]), "r"(a[1]), "r"(a[2]), "r"(a[3]), "r"(b[0]), "r"(b[1]));
}

__device__ __forceinline__ uint32_t smaddr(const void* p) {
    return (uint32_t)__cvta_generic_to_shared(p);
}
__device__ __forceinline__ void cpa16(uint32_t dst_s, const void* src, bool valid) {
    // NOTE: valid=false still WRITES 16 zero bytes to dst (zero-fill), use only
    // where zero-padding the destination is intended.
    int sz = valid ? 16 : 0;
    asm volatile("cp.async.cg.shared.global [%0], [%1], 16, %2;\n"
                 :: "r"(dst_s), "l"(src), "r"(sz));
}
__device__ __forceinline__ void cpa_commit() {
    asm volatile("cp.async.commit_group;\n");
}
template <int N>
__device__ __forceinline__ void cpa_wait() {
    asm volatile("cp.async.wait_group %0;\n" :: "n"(N));
}

// ---------------------------------------------------------------------------
// prep: fold BN; emit fragment-ordered packed-bf16 hi/lo weights.
// ---------------------------------------------------------------------------
__global__ void prep_kernel(const float* __restrict__ expand_w,
                            const float* __restrict__ expand_bn,
                            const float* __restrict__ dw_w,
                            const float* __restrict__ dw_bn,
                            const float* __restrict__ id_w,
                            const float* __restrict__ id_bn,
                            const float* __restrict__ merge_bn,
                            const float* __restrict__ proj_w,
                            const float* __restrict__ proj_bn) {
    int tid = blockIdx.x * blockDim.x + threadIdx.x;
    int nth = gridDim.x * blockDim.x;

    for (int idx = tid; idx < 18432; idx += nth) {
        int q = idx & 3, lane = (idx >> 2) & 31, hl = (idx >> 7) & 1;
        int t = idx >> 8;
        int mi = t & 1; t >>= 1;
        int ki = t % 6; t /= 6;
        int wr = t & 1; t >>= 1;
        int mt = t;
        int m = mt * 64 + wr * 32 + mi * 16 + (lane >> 2) + 8 * (q & 1);
        int k = ki * 16 + (lane & 3) * 2 + 8 * (q >> 1);
        float sc = expand_bn[m] * rsqrtf(expand_bn[3 * MIDC + m] + EPSBN);
        float w0 = expand_w[m * CINC + k] * sc;
        float w1 = expand_w[m * CINC + k + 1] * sc;
        float h0 = bf16hi(w0), h1 = bf16hi(w1);
        g_WexpF[idx] = hl ? packbf2(w0 - h0, w1 - h1) : packbf2(h0, h1);
    }
    for (int idx = tid; idx < 18432; idx += nth) {
        int q = idx & 3, lane = (idx >> 2) & 31, hl = (idx >> 7) & 1;
        int t = idx >> 8;
        int mi = t % 3; t /= 3;
        int ki = t % 3; t /= 3;
        int wr = t & 1; int chunk = t >> 1;
        int m = wr * 48 + mi * 16 + (lane >> 2) + 8 * (q & 1);
        int k = chunk * 48 + ki * 16 + (lane & 3) * 2 + 8 * (q >> 1);
        float sc = proj_bn[m] * rsqrtf(proj_bn[3 * COUTC + m] + EPSBN);
        float w0 = proj_w[m * MIDC + k] * sc;
        float w1 = proj_w[m * MIDC + k + 1] * sc;
        float h0 = bf16hi(w0), h1 = bf16hi(w1);
        g_WprojF[idx] = hl ? packbf2(w0 - h0, w1 - h1) : packbf2(h0, h1);
    }
    for (int o = tid; o < MIDC; o += nth) {
        float sc = expand_bn[o] * rsqrtf(expand_bn[3 * MIDC + o] + EPSBN);
        g_bexp[o] = expand_bn[MIDC + o] - expand_bn[2 * MIDC + o] * sc;
    }
    for (int c = tid; c < MIDC; c += nth) {
        float dsc = dw_bn[c] * rsqrtf(dw_bn[3 * MIDC + c] + EPSBN);
        float dsh = dw_bn[MIDC + c] - dw_bn[2 * MIDC + c] * dsc;
        float isc = id_bn[c] * rsqrtf(id_bn[3 * MIDC + c] + EPSBN);
        float ish = id_bn[MIDC + c] - id_bn[2 * MIDC + c] * isc;
        float msc = merge_bn[c] * rsqrtf(merge_bn[3 * MIDC + c] + EPSBN);
        float msh = merge_bn[MIDC + c] - merge_bn[2 * MIDC + c] * msc;
        #pragma unroll
        for (int k = 0; k < 9; k++) g_W9[c * 9 + k] = msc * dsc * dw_w[c * 9 + k];
        g_W9[c * 9 + 4] += msc * isc * id_w[c];
        g_T[c] = msc * (dsh + ish) + msh;
    }
    for (int o = tid; o < COUTC; o += nth) {
        float sc = proj_bn[o] * rsqrtf(proj_bn[3 * COUTC + o] + EPSBN);
        g_bproj[o] = proj_bn[COUTC + o] - proj_bn[2 * COUTC + o] * sc;
    }
}

// ---------------------------------------------------------------------------
// Expand 1x1 GEMM. 192(Mx3 passes) x 128(N); warp tile 32x32; bf16 k16.
// A depth-2 cp.async pipeline; B converted once at start. fp16 output.
// ---------------------------------------------------------------------------
__global__ void __launch_bounds__(256, 2) expand_gemm(const float* __restrict__ x) {
    extern __shared__ uint32_t smu[];
    uint32_t* As0 = smu;                    // EXP_A_U32
    uint32_t* As1 = smu + EXP_A_U32;
    uint32_t* Bh  = smu + 2 * EXP_A_U32;    // EXP_B_U32
    uint32_t* Bl  = Bh + EXP_B_U32;
    int b = blockIdx.z;
    int p0 = blockIdx.x * 128;
    int tid = threadIdx.x;
    int lane = tid & 31, w = tid >> 5;
    int wr = w >> 2, wc = w & 3;
    int g = lane >> 2, tg = lane & 3;
    const float* xb = x + (size_t)b * CINC * HWP;
    __half* ob = g_mid + (size_t)b * MIDC * HWP;

    // Prefetch A(0) and A(1) upfront (two commit groups)
    {
        const uint4* src = (const uint4*)g_WexpF;
        #pragma unroll
        for (int j = 0; j < 6; j++)
            cpa16(smaddr(As0) + (tid + j * 256) * 16, src + tid + j * 256, true);
        cpa_commit();
        src += EXP_A_U32 / 4;
        #pragma unroll
        for (int j = 0; j < 6; j++)
            cpa16(smaddr(As1) + (tid + j * 256) * 16, src + tid + j * 256, true);
        cpa_commit();
    }
    // Convert B (overlaps both A fetches)
    #pragma unroll
    for (int j = 0; j < 6; j++) {
        int v = tid + j * 256;
        int k2 = v >> 5, c4 = (v & 31) << 2;
        int p = p0 + c4;
        float4 r0 = make_float4(0.f, 0.f, 0.f, 0.f), r1 = r0;
        if (p < HWP) {
            r0 = *(const float4*)&xb[(size_t)(2 * k2) * HWP + p];
            r1 = *(const float4*)&xb[(size_t)(2 * k2 + 1) * HWP + p];
        }
        float e0[4] = {r0.x, r0.y, r0.z, r0.w};
        float e1[4] = {r1.x, r1.y, r1.z, r1.w};
        uint32_t hh[4], ll[4];
        #pragma unroll
        for (int i = 0; i < 4; i++) {
            float h0 = bf16hi(e0[i]), h1 = bf16hi(e1[i]);
            hh[i] = packbf2(h0, h1);
            ll[i] = packbf2(e0[i] - h0, e1[i] - h1);
        }
        *(uint4*)&Bh[k2 * BSS + c4] = make_uint4(hh[0], hh[1], hh[2], hh[3]);
        *(uint4*)&Bl[k2 * BSS + c4] = make_uint4(ll[0], ll[1], ll[2], ll[3]);
    }

    for (int mt = 0; mt < 3; mt++) {
        uint32_t* Acur = (mt & 1) ? As1 : As0;
        if (mt == 2) { cpa_wait<0>(); } else { cpa_wait<1>(); }
        __syncthreads();   // A(mt) visible; B visible (mt=0); prev buffer free

        float acc[2][4][4] = {};
        #pragma unroll
        for (int ki = 0; ki < 6; ki++) {
            uint4 ah[2], al[2];
            #pragma unroll
            for (int mi = 0; mi < 2; mi++) {
                int off = (((wr * 6 + ki) * 2 + mi) * 2) * 128 + lane * 4;
                ah[mi] = *(const uint4*)&Acur[off];
                al[mi] = *(const uint4*)&Acur[off + 128];
            }
            uint32_t bh[4][2], bl[4][2];
            int kr2 = ki * 8;
            #pragma unroll
            for (int ni = 0; ni < 4; ni++) {
                int nb = wc * 32 + ni * 8 + g;
                bh[ni][0] = Bh[(kr2 + tg) * BSS + nb];
                bh[ni][1] = Bh[(kr2 + tg + 4) * BSS + nb];
                bl[ni][0] = Bl[(kr2 + tg) * BSS + nb];
                bl[ni][1] = Bl[(kr2 + tg + 4) * BSS + nb];
            }
            #pragma unroll
            for (int mi = 0; mi < 2; mi++)
                #pragma unroll
                for (int ni = 0; ni < 4; ni++) {
                    mma16(acc[mi][ni], (const uint32_t*)&ah[mi], bh[ni]);
                    mma16(acc[mi][ni], (const uint32_t*)&al[mi], bh[ni]);
                    mma16(acc[mi][ni], (const uint32_t*)&ah[mi], bl[ni]);
                }
        }

        int m0 = mt * 64;
        #pragma unroll
        for (int mi = 0; mi < 2; mi++) {
            int o = m0 + wr * 32 + mi * 16 + g;
            float b0f = g_bexp[o], b1f = g_bexp[o + 8];
            #pragma unroll
            for (int ni = 0; ni < 4; ni++) {
                int p = p0 + wc * 32 + ni * 8 + tg * 2;
                if (p < HWP) {
                    *(__half2*)&ob[(size_t)o * HWP + p] =
                        __floats2half2_rn(silu_f(acc[mi][ni][0] + b0f),
                                          silu_f(acc[mi][ni][1] + b0f));
                    *(__half2*)&ob[(size_t)(o + 8) * HWP + p] =
                        __floats2half2_rn(silu_f(acc[mi][ni][2] + b1f),
                                          silu_f(acc[mi][ni][3] + b1f));
                }
            }
        }
        __syncthreads();   // all reads of Acur done before refill
        if (mt == 0) {
            const uint4* src = ((const uint4*)g_WexpF) + 2 * (EXP_A_U32 / 4);
            #pragma unroll
            for (int j = 0; j < 6; j++)
                cpa16(smaddr(As0) + (tid + j * 256) * 16, src + tid + j * 256, true);
            cpa_commit();
        }
    }
}

// ---------------------------------------------------------------------------
// dwmerge v3: border-only zeroing (exactly the cells the shifted fill never
// writes -> same phase as fill, no extra barrier). Pass-3 pad fix after sync.
// ---------------------------------------------------------------------------
#define SROW 64
__global__ void __launch_bounds__(256) dwmerge_kernel() {
    __shared__ float sps[2][58 * SROW];
    __shared__ float sred[16];
    int bc = blockIdx.x;
    int b = bc / 96, k2 = bc - b * 96;
    int tid = threadIdx.x;

    int oyA[2], oxA[2];
    const __half* planes[2];
    float w9[2][9], T[2];
    #pragma unroll
    for (int ch = 0; ch < 2; ch++) {
        int c = 2 * k2 + ch;
        int cpre = (c & 3) * 48 + (c >> 2);
        int gg = c & 3;
        oyA[ch] = (gg == 0) ? -1 : (gg == 2) ? 1 : 0;
        oxA[ch] = (gg == 1) ? -1 : (gg == 3) ? 1 : 0;
        planes[ch] = g_mid + ((size_t)b * MIDC + cpre) * HWP;
        #pragma unroll
        for (int k = 0; k < 9; k++) w9[ch][k] = g_W9[c * 9 + k];
        T[ch] = g_T[c];
    }

    // Phase A (no internal sync needed — all writes disjoint):
    //  (1) fill valid rows with shifted data at col offset OFF=5-ox
    //  (2) zero the never-written border rows/cols
    for (int t = tid; t < 1624; t += 256) {
        int ch = t >= 812;
        int u = t - ch * 812;
        int r = u / 14, qq = u - r * 14;
        int hp = r - 1, hs = hp + oyA[ch];
        if ((unsigned)hp < 56u && (unsigned)hs < 56u) {
            uint2 v = *(const uint2*)&planes[ch][hs * 56 + qq * 4];
            float2 f01 = __half22float2(*(__half2*)&v.x);
            float2 f23 = __half22float2(*(__half2*)&v.y);
            float* d = &sps[ch][r * SROW + qq * 4 + (5 - oxA[ch])];
            d[0] = f01.x; d[1] = f01.y; d[2] = f23.x; d[3] = f23.y;
        }
    }
    // Border rows: rows never written by the fill (exact per oy)
    // oy=0: {0,57}; oy=-1: {0,1,57}; oy=1: {0,56,57}.  3 slots; slot 2 may dup row 0.
    for (int t = tid; t < 2 * 3 * 16; t += 256) {
        int ch = t >= 48;
        int u = t - ch * 48;
        int slot = u >> 4, c4 = (u & 15) << 2;
        int oy = oyA[ch];
        int rr = (slot == 0) ? 0 : (slot == 1) ? 57
                : (oy == -1) ? 1 : (oy == 1) ? 56 : 0;   // oy==0: dup row 0 (harmless)
        *(float4*)&sps[ch][rr * SROW + c4] = make_float4(0.f, 0.f, 0.f, 0.f);
    }
    // Border cols: cols in the read range [4,61] never written by the fill.
    // ox=0: {4,61}; ox=1: {60,61}; ox=-1: {4,5}.
    for (int t = tid; t < 2 * 2 * 58; t += 256) {
        int ch = t >= 116;
        int u = t - ch * 116;
        int which = u >= 58;
        int rr = u - which * 58;
        int ox = oxA[ch];
        int cc = (ox == 0) ? (which ? 61 : 4)
               : (ox == 1) ? (which ? 61 : 60)
                           : (which ? 5 : 4);
        sps[ch][rr * SROW + cc] = 0.f;
    }
    __syncthreads();

    // Pass 3: zero the conv-pad cell that the shifted copy DID fill
    if (tid < 116) {
        int ch = tid >= 58;
        int r = tid - ch * 58;
        int ox = oxA[ch];
        if (ox == 1)  sps[ch][r * SROW + 4] = 0.f;   // wp=-1 cell
        if (ox == -1) sps[ch][r * SROW + 61] = 0.f;  // wp=56 cell
    }
    __syncthreads();

    uint32_t* oH = g_mergedH + ((size_t)b * 96 + k2) * HWP;
    uint32_t* oL = g_mergedL + ((size_t)b * 96 + k2) * HWP;
    float ls0 = 0.f, ls1 = 0.f;

    for (int t = tid; t < 784; t += 256) {
        int h = t / 14, q = t - h * 14;
        float a0[4] = {T[0], T[0], T[0], T[0]};
        float a1[4] = {T[1], T[1], T[1], T[1]};
        #pragma unroll
        for (int ch = 0; ch < 2; ch++) {
            float* accp = ch ? a1 : a0;
            #pragma unroll
            for (int dy = 0; dy < 3; dy++) {
                const float* row = &sps[ch][(h + dy) * SROW + q * 4 + 4];
                float4 A = *(const float4*)row;
                float2 Bv = *(const float2*)(row + 4);
                float wA = w9[ch][dy * 3], wB = w9[ch][dy * 3 + 1], wC = w9[ch][dy * 3 + 2];
                accp[0] += wA * A.x + wB * A.y + wC * A.z;
                accp[1] += wA * A.y + wB * A.z + wC * A.w;
                accp[2] += wA * A.z + wB * A.w + wC * Bv.x;
                accp[3] += wA * A.w + wB * Bv.x + wC * Bv.y;
            }
        }
        uint32_t Hw[4], Lw[4];
        #pragma unroll
        for (int i = 0; i < 4; i++) {
            float s0 = silu_f(a0[i]);
            float s1 = silu_f(a1[i]);
            float h0 = bf16hi(s0), h1 = bf16hi(s1);
            Hw[i] = packbf2(h0, h1);
            Lw[i] = packbf2(s0 - h0, s1 - h1);
            ls0 += s0;
            ls1 += s1;
        }
        int o = h * 56 + q * 4;
        *(uint4*)&oH[o] = make_uint4(Hw[0], Hw[1], Hw[2], Hw[3]);
        *(uint4*)&oL[o] = make_uint4(Lw[0], Lw[1], Lw[2], Lw[3]);
    }

    int wid = tid >> 5, lane = tid & 31;
    #pragma unroll
    for (int o = 16; o > 0; o >>= 1) {
        ls0 += __shfl_down_sync(0xffffffffu, ls0, o);
        ls1 += __shfl_down_sync(0xffffffffu, ls1, o);
    }
    if (lane == 0) { sred[wid] = ls0; sred[8 + wid] = ls1; }
    __syncthreads();
    if (tid < 16) {
        float v = sred[tid];
        #pragma unroll
        for (int o = 4; o > 0; o >>= 1) v += __shfl_down_sync(0xffffu, v, o);
        if (tid == 0) g_sums[b * 192 + 2 * k2] = v;
        if (tid == 8) g_sums[b * 192 + 2 * k2 + 1] = v;
    }
}

// ---------------------------------------------------------------------------
// SE gating + per-batch scaled/resplit proj weights. Block = (batch, chunk).
// ---------------------------------------------------------------------------
__global__ void __launch_bounds__(256) se_scale_kernel(const float* __restrict__ red_w,
                                                       const float* __restrict__ red_b,
                                                       const float* __restrict__ exp_w,
                                                       const float* __restrict__ exp_b) {
    __shared__ float smean[192];
    __shared__ float sredu[24];
    __shared__ float s_se[192];
    int b = blockIdx.x, cc = blockIdx.y;
    int tid = threadIdx.x;

    if (tid < 192) smean[tid] = g_sums[b * 192 + tid] * (1.f / 3136.f);
    __syncthreads();
    if (tid < 24) {
        int gq = tid >> 1;
        float a = red_b[tid];
        #pragma unroll
        for (int i = 0; i < 16; i++) a += red_w[tid * 16 + i] * smean[gq * 16 + i];
        sredu[tid] = fmaxf(a, 0.f);
    }
    __syncthreads();
    if (tid < 192) {
        int gq = tid >> 4;
        float v = exp_w[tid * 2] * sredu[gq * 2] + exp_w[tid * 2 + 1] * sredu[gq * 2 + 1]
                + exp_b[tid];
        s_se[tid] = 1.f / (1.f + __expf(-v));
    }
    __syncthreads();

    uint32_t* dstb = g_WprojSE + (size_t)b * 18432;
    const uint4* src = ((const uint4*)g_WprojF) + cc * (PROJ_A_U32 / 4);
    uint4* dst = ((uint4*)dstb) + cc * (PROJ_A_U32 / 4);
    for (int i = tid; i < 576; i += 256) {
        int grp = i >> 5, li = i & 31;
        int ki = (grp / 3) % 3;
        uint4 H = src[grp * 64 + li];
        uint4 L = src[grp * 64 + li + 32];
        int k2a = cc * 24 + ki * 8 + (li & 3);
        float se0 = s_se[2 * k2a], se1 = s_se[2 * k2a + 1];
        float se2 = s_se[2 * k2a + 8], se3 = s_se[2 * k2a + 9];
        uint32_t hu[4] = {H.x, H.y, H.z, H.w};
        uint32_t lu[4] = {L.x, L.y, L.z, L.w};
        uint32_t nh[4], nl[4];
        #pragma unroll
        for (int q = 0; q < 4; q++) {
            float sA = (q < 2) ? se0 : se2;
            float sB = (q < 2) ? se1 : se3;
            float2 hf = unpackbf2(hu[q]);
            float2 lf = unpackbf2(lu[q]);
            float v0 = (hf.x + lf.x) * sA;
            float v1 = (hf.y + lf.y) * sB;
            float h0 = bf16hi(v0), h1 = bf16hi(v1);
            nh[q] = packbf2(h0, h1);
            nl[q] = packbf2(v0 - h0, v1 - h1);
        }
        dst[grp * 64 + li]      = make_uint4(nh[0], nh[1], nh[2], nh[3]);
        dst[grp * 64 + li + 32] = make_uint4(nl[0], nl[1], nl[2], nl[3]);
    }
}

// ---------------------------------------------------------------------------
// Project 1x1 GEMM (round-12 proven version). M=96 x N=128; 4 k-chunks of 48;
// depth-2 cp.async pipeline; residual x prefetched into freed smem during
// last chunk.
// ---------------------------------------------------------------------------
__global__ void __launch_bounds__(256, 2) proj_gemm(const float* __restrict__ x,
                                                    float* __restrict__ out) {
    extern __shared__ uint32_t smu[];
    uint32_t* As0 = smu;                        // PROJ_A_U32
    uint32_t* As1 = smu + PROJ_A_U32;
    uint32_t* Bst = smu + 2 * PROJ_A_U32;       // 2 stages x 2 planes x PROJ_B_U32

    int b = blockIdx.z;
    int p0 = blockIdx.x * 128;
    int tid = threadIdx.x;
    int lane = tid & 31, w = tid >> 5;
    int wr = w >> 2, wc = w & 3;
    int g = lane >> 2, tg = lane & 3;
    const uint32_t* mH = g_mergedH + (size_t)b * 96 * HWP;
    const uint32_t* mL = g_mergedL + (size_t)b * 96 * HWP;
    const uint4* Asrc = (const uint4*)(g_WprojSE + (size_t)b * 18432);
    const float* xb = x + (size_t)b * COUTC * HWP;

    auto cp_stage = [&](int c) {
        int stage = c & 1;
        uint32_t dstB = smaddr(Bst) + stage * 2 * PROJ_B_U32 * 4;
        const uint4* sH = (const uint4*)(mH + (size_t)(c * 24) * HWP);
        const uint4* sL = (const uint4*)(mL + (size_t)(c * 24) * HWP);
        #pragma unroll
        for (int j = 0; j < 3; j++) {
            int v = tid + j * 256;
            int r = v >> 5, c4 = (v & 31);
            int p = p0 + c4 * 4;
            bool ok = p < HWP;                  // zero-fill pad (intended)
            size_t so = (size_t)r * (HWP / 4) + (p0 >> 2) + c4;
            uint32_t d = dstB + (r * BSS + c4 * 4) * 4;
            cpa16(d, sH + (ok ? so : 0), ok);
            cpa16(d + PROJ_B_U32 * 4, sL + (ok ? so : 0), ok);
        }
        // A chunk: 1152 uint4 = 4*256 + 128 exact
        uint32_t dstA = smaddr(stage ? As1 : As0);
        const uint4* sA = Asrc + c * (PROJ_A_U32 / 4);
        #pragma unroll
        for (int j = 0; j < 4; j++) {
            int v = tid + j * 256;
            cpa16(dstA + v * 16, sA + v, true);
        }
        if (tid < 128) {
            int v = tid + 1024;
            cpa16(dstA + v * 16, sA + v, true);
        }
        cpa_commit();
    };
    cp_stage(0);
    cp_stage(1);

    float acc[3][4][4] = {};

    for (int c = 0; c < 4; c++) {
        uint32_t* Acur = (c & 1) ? As1 : As0;
        uint32_t* BhS = Bst + (c & 1) * 2 * PROJ_B_U32;
        uint32_t* BlS = BhS + PROJ_B_U32;
        cpa_wait<1>();        // chunk c complete (FIFO); c+1 may be in flight
        __syncthreads();

        #pragma unroll
        for (int ki = 0; ki < 3; ki++) {
            uint4 ah[3], al[3];
            #pragma unroll
            for (int mi = 0; mi < 3; mi++) {
                int off = ((wr * 3 + ki) * 3 + mi) * 256 + lane * 4;
                ah[mi] = *(const uint4*)&Acur[off];
                al[mi] = *(const uint4*)&Acur[off + 128];
            }
            uint32_t bh[4][2], bl[4][2];
            int kr2 = ki * 8;
            #pragma unroll
            for (int ni = 0; ni < 4; ni++) {
                int nb = wc * 32 + ni * 8 + g;
                bh[ni][0] = BhS[(kr2 + tg) * BSS + nb];
                bh[ni][1] = BhS[(kr2 + tg + 4) * BSS + nb];
                bl[ni][0] = BlS[(kr2 + tg) * BSS + nb];
                bl[ni][1] = BlS[(kr2 + tg + 4) * BSS + nb];
            }
            #pragma unroll
            for (int mi = 0; mi < 3; mi++)
                #pragma unroll
                for (int ni = 0; ni < 4; ni++) {
                    mma16(acc[mi][ni], (const uint32_t*)&ah[mi], bh[ni]);
                    mma16(acc[mi][ni], (const uint32_t*)&al[mi], bh[ni]);
                    mma16(acc[mi][ni], (const uint32_t*)&ah[mi], bl[ni]);
                }
        }
        __syncthreads();      // buffer (c&1) now free for refill

        if (c < 2) {
            cp_stage(c + 2);
        } else if (c == 2) {
            // Prefetch x rows 0..86 into As0 + Bst stage0 (44544 B = 2784 uint4)
            #pragma unroll
            for (int j = 0; j < 11; j++) {
                int t = tid + j * 256;
                if (t < 2784) {
                    int row = t >> 5, c4 = t & 31;
                    int p = p0 + c4 * 4;
                    int idx = row * 128 + c4 * 4;               // u32 index
                    uint32_t off = (idx < PROJ_A_U32) ? (uint32_t)idx
                                                      : (uint32_t)(idx + PROJ_A_U32);
                    cpa16(smaddr(smu) + off * 4,
                          xb + (size_t)row * HWP + p, p < HWP);
                }
            }
            cpa_commit();
        }
    }
    cpa_wait<0>();   // x prefetch complete
    __syncthreads();

    float* ob = out + (size_t)b * COUTC * HWP;
    #pragma unroll
    for (int mi = 0; mi < 3; mi++) {
        int o = wr * 48 + mi * 16 + g;
        float b0f = g_bproj[o], b1f = g_bproj[o + 8];
        #pragma unroll
        for (int ni = 0; ni < 4; ni++) {
            int pp = wc * 32 + ni * 8 + tg * 2;
            int p = p0 + pp;
            if (p < HWP) {
                float2 x0, x1;
                {
                    int idx = o * 128 + pp;
                    uint32_t off = (idx < PROJ_A_U32) ? (uint32_t)idx
                                                      : (uint32_t)(idx + PROJ_A_U32);
                    x0 = (o < 87) ? make_float2(__uint_as_float(smu[off]),
                                                __uint_as_float(smu[off + 1]))
                                  : *(const float2*)&xb[(size_t)o * HWP + p];
                }
                {
                    int o2 = o + 8;
                    int idx = o2 * 128 + pp;
                    uint32_t off = (idx < PROJ_A_U32) ? (uint32_t)idx
                                                      : (uint32_t)(idx + PROJ_A_U32);
                    x1 = (o2 < 87) ? make_float2(__uint_as_float(smu[off]),
                                                 __uint_as_float(smu[off + 1]))
                                   : *(const float2*)&xb[(size_t)(o + 8) * HWP + p];
                }
                float2 r0;
                r0.x = silu_f(acc[mi][ni][0] + b0f + x0.x);
                r0.y = silu_f(acc[mi][ni][1] + b0f + x0.y);
                *(float2*)&ob[(size_t)o * HWP + p] = r0;
                float2 r1;
                r1.x = silu_f(acc[mi][ni][2] + b1f + x1.x);
                r1.y = silu_f(acc[mi][ni][3] + b1f + x1.y);
                *(float2*)&ob[(size_t)(o + 8) * HWP + p] = r1;
            }
        }
    }
}

// ---------------------------------------------------------------------------
extern "C" void kernel_launch(void* const* d_in, const int* in_sizes, int n_in,
                              void* d_out, int out_size) {
    const float* x         = (const float*)d_in[0];
    const float* expand_w  = (const float*)d_in[1];
    const float* expand_bn = (const float*)d_in[2];
    const float* dw_w      = (const float*)d_in[3];
    const float* dw_bn     = (const float*)d_in[4];
    const float* id_w      = (const float*)d_in[5];
    const float* id_bn     = (const float*)d_in[6];
    const float* merge_bn  = (const float*)d_in[7];
    const float* se_red_w  = (const float*)d_in[8];
    const float* se_red_b  = (const float*)d_in[9];
    const float* se_exp_w  = (const float*)d_in[10];
    const float* se_exp_b  = (const float*)d_in[11];
    const float* proj_w    = (const float*)d_in[12];
    const float* proj_bn   = (const float*)d_in[13];
    float* out = (float*)d_out;

    cudaFuncSetAttribute(expand_gemm, cudaFuncAttributeMaxDynamicSharedMemorySize, EXP_SMEM);
    cudaFuncSetAttribute(proj_gemm,   cudaFuncAttributeMaxDynamicSharedMemorySize, PROJ_SMEM);

    prep_kernel<<<264, 256>>>(expand_w, expand_bn, dw_w, dw_bn, id_w, id_bn,
                              merge_bn, proj_w, proj_bn);
    expand_gemm<<<dim3(25, 1, BZ), 256, EXP_SMEM>>>(x);
    dwmerge_kernel<<<BZ * 96, 256>>>();
    se_scale_kernel<<<dim3(BZ, 4), 256>>>(se_red_w, se_red_b, se_exp_w, se_exp_b);
    proj_gemm<<<dim3(25, 1, BZ), 256, PROJ_SMEM>>>(x, out);
}

// round 15
// speedup vs baseline: 1.3637x; 1.0435x over previous
#include <cuda_runtime.h>
#include <cuda_bf16.h>
#include <cuda_fp16.h>
#include <math.h>
#include <stdint.h>

#define BZ    64
#define CINC  96
#define COUTC 96
#define MIDC  192
#define HWP   3136
#define EPSBN 1e-5f

#define BSS 136                    // pair-row stride (u32): bank = 8*tg+g, conflict-free
#define EXP_A_U32   6144           // per-mt A chunk  [wr2][ki6][mi2][hl2][lane32][q4]
#define PROJ_A_U32  4608           // per-kchunk A    [wr2][ki3][mi3][hl2][lane32][q4]
#define EXP_B_U32   (48 * BSS)     // one plane (hi or lo), 48 pair-rows
#define PROJ_B_U32  (24 * BSS)     // single fp16 plane per chunk, 24 pair-rows
#define EXP_SMEM  ((2 * EXP_A_U32 + 2 * EXP_B_U32) * 4)      // 101376 B
#define PROJ_SMEM ((2 * PROJ_A_U32 + 2 * PROJ_B_U32) * 4)    // 62976 B

// Scratch (device globals: allowed; no cudaMalloc anywhere)
__device__ __align__(16) __half   g_mid[(size_t)BZ * MIDC * HWP];    // fp16 mid
__device__ __align__(16) uint32_t g_mergedF[(size_t)BZ * 96 * HWP];  // packed fp16 (c,c+1)
__device__ float    g_sums[BZ * MIDC];
__device__ __align__(16) uint32_t g_WexpF[18432];   // [mt3][wr2][ki6][mi2][hl2][lane32][q4] bf16
__device__ __align__(16) uint32_t g_WprojF[18432];  // [chunk4][wr2][ki3][mi3][hl2][lane32][q4] bf16
__device__ __align__(16) uint32_t g_WprojSE[(size_t)BZ * 18432];  // per-batch SE-scaled fp16 hi/lo
__device__ float    g_bexp[MIDC];
__device__ float    g_W9[MIDC * 9];
__device__ float    g_T[MIDC];
__device__ float    g_bproj[COUTC];

__device__ __forceinline__ float silu_f(float v) { return v / (1.f + __expf(-v)); }

__device__ __forceinline__ uint32_t packbf2(float lo_elem, float hi_elem) {
    __nv_bfloat162 t = __floats2bfloat162_rn(lo_elem, hi_elem);  // .x = low 16 bits
    return *(uint32_t*)&t;
}
__device__ __forceinline__ uint32_t packfp2(float lo_elem, float hi_elem) {
    __half2 t = __floats2half2_rn(lo_elem, hi_elem);             // .x = low 16 bits
    return *(uint32_t*)&t;
}
__device__ __forceinline__ float2 unpackbf2(uint32_t u) {
    __nv_bfloat162 t = *(__nv_bfloat162*)&u;
    return __bfloat1622float2(t);
}
__device__ __forceinline__ float bf16hi(float v) {
    return __bfloat162float(__float2bfloat16_rn(v));
}
__device__ __forceinline__ float fp16hi(float v) {
    return __half2float(__float2half_rn(v));
}

__device__ __forceinline__ void mma16(float* c, const uint32_t* a, const uint32_t* b) {
    asm volatile(
        "mma.sync.aligned.m16n8k16.row.col.f32.bf16.bf16.f32 "
        "{%0,%1,%2,%3},{%4,%5,%6,%7},{%8,%9},{%0,%1,%2,%3};"
        : "+f"(c[0]), "+f"(c[1]), "+f"(c[2]), "+f"(c[3])
        : "r"(a[0]), "r"(a[1]), "r"(a[2]), "r"(a[3]), "r"(b[0]), "r"(b[1]));
}
__device__ __forceinline__ void mma16f(float* c, const uint32_t* a, const uint32_t* b) {
    asm volatile(
        "mma.sync.aligned.m16n8k16.row.col.f32.f16.f16.f32 "
        "{%0,%1,%2,%3},{%4,%5,%6,%7},{%8,%9},{%0,%1,%2,%3};"
        : "+f"(c[0]), "+f"(c[1]), "+f"(c[2]), "+f"(c[3])
        : "r"(a[0]), "r"(a[1]), "r"(a[2]), "r"(a[3]), "r"(b[0]), "r"(b[1]));
}

__device__ __forceinline__ uint32_t smaddr(const void* p) {
    return (uint32_t)__cvta_generic_to_shared(p);
}
__device__ __forceinline__ void cpa16(uint32_t dst_s, const void* src, bool valid) {
    // NOTE: valid=false still WRITES 16 zero bytes to dst (zero-fill).
    int sz = valid ? 16 : 0;
    asm volatile("cp.async.cg.shared.global [%0], [%1], 16, %2;\n"
                 :: "r"(dst_s), "l"(src), "r"(sz));
}
__device__ __forceinline__ void cpa_commit() {
    asm volatile("cp.async.commit_group;\n");
}
template <int N>
__device__ __forceinline__ void cpa_wait() {
    asm volatile("cp.async.wait_group %0;\n" :: "n"(N));
}

// ---------------------------------------------------------------------------
// prep: fold BN; emit fragment-ordered packed-bf16 hi/lo weights.
// ---------------------------------------------------------------------------
__global__ void prep_kernel(const float* __restrict__ expand_w,
                            const float* __restrict__ expand_bn,
                            const float* __restrict__ dw_w,
                            const float* __restrict__ dw_bn,
                            const float* __restrict__ id_w,
                            const float* __restrict__ id_bn,
                            const float* __restrict__ merge_bn,
                            const float* __restrict__ proj_w,
                            const float* __restrict__ proj_bn) {
    int tid = blockIdx.x * blockDim.x + threadIdx.x;
    int nth = gridDim.x * blockDim.x;

    for (int idx = tid; idx < 18432; idx += nth) {
        int q = idx & 3, lane = (idx >> 2) & 31, hl = (idx >> 7) & 1;
        int t = idx >> 8;
        int mi = t & 1; t >>= 1;
        int ki = t % 6; t /= 6;
        int wr = t & 1; t >>= 1;
        int mt = t;
        int m = mt * 64 + wr * 32 + mi * 16 + (lane >> 2) + 8 * (q & 1);
        int k = ki * 16 + (lane & 3) * 2 + 8 * (q >> 1);
        float sc = expand_bn[m] * rsqrtf(expand_bn[3 * MIDC + m] + EPSBN);
        float w0 = expand_w[m * CINC + k] * sc;
        float w1 = expand_w[m * CINC + k + 1] * sc;
        float h0 = bf16hi(w0), h1 = bf16hi(w1);
        g_WexpF[idx] = hl ? packbf2(w0 - h0, w1 - h1) : packbf2(h0, h1);
    }
    for (int idx = tid; idx < 18432; idx += nth) {
        int q = idx & 3, lane = (idx >> 2) & 31, hl = (idx >> 7) & 1;
        int t = idx >> 8;
        int mi = t % 3; t /= 3;
        int ki = t % 3; t /= 3;
        int wr = t & 1; int chunk = t >> 1;
        int m = wr * 48 + mi * 16 + (lane >> 2) + 8 * (q & 1);
        int k = chunk * 48 + ki * 16 + (lane & 3) * 2 + 8 * (q >> 1);
        float sc = proj_bn[m] * rsqrtf(proj_bn[3 * COUTC + m] + EPSBN);
        float w0 = proj_w[m * MIDC + k] * sc;
        float w1 = proj_w[m * MIDC + k + 1] * sc;
        float h0 = bf16hi(w0), h1 = bf16hi(w1);
        g_WprojF[idx] = hl ? packbf2(w0 - h0, w1 - h1) : packbf2(h0, h1);
    }
    for (int o = tid; o < MIDC; o += nth) {
        float sc = expand_bn[o] * rsqrtf(expand_bn[3 * MIDC + o] + EPSBN);
        g_bexp[o] = expand_bn[MIDC + o] - expand_bn[2 * MIDC + o] * sc;
    }
    for (int c = tid; c < MIDC; c += nth) {
        float dsc = dw_bn[c] * rsqrtf(dw_bn[3 * MIDC + c] + EPSBN);
        float dsh = dw_bn[MIDC + c] - dw_bn[2 * MIDC + c] * dsc;
        float isc = id_bn[c] * rsqrtf(id_bn[3 * MIDC + c] + EPSBN);
        float ish = id_bn[MIDC + c] - id_bn[2 * MIDC + c] * isc;
        float msc = merge_bn[c] * rsqrtf(merge_bn[3 * MIDC + c] + EPSBN);
        float msh = merge_bn[MIDC + c] - merge_bn[2 * MIDC + c] * msc;
        #pragma unroll
        for (int k = 0; k < 9; k++) g_W9[c * 9 + k] = msc * dsc * dw_w[c * 9 + k];
        g_W9[c * 9 + 4] += msc * isc * id_w[c];
        g_T[c] = msc * (dsh + ish) + msh;
    }
    for (int o = tid; o < COUTC; o += nth) {
        float sc = proj_bn[o] * rsqrtf(proj_bn[3 * COUTC + o] + EPSBN);
        g_bproj[o] = proj_bn[COUTC + o] - proj_bn[2 * COUTC + o] * sc;
    }
}

// ---------------------------------------------------------------------------
// Expand 1x1 GEMM. 192(Mx3 passes) x 128(N); warp tile 32x32; bf16 k16.
// A depth-2 cp.async pipeline; B converted once at start. fp16 output.
// ---------------------------------------------------------------------------
__global__ void __launch_bounds__(256, 2) expand_gemm(const float* __restrict__ x) {
    extern __shared__ uint32_t smu[];
    uint32_t* As0 = smu;                    // EXP_A_U32
    uint32_t* As1 = smu + EXP_A_U32;
    uint32_t* Bh  = smu + 2 * EXP_A_U32;    // EXP_B_U32
    uint32_t* Bl  = Bh + EXP_B_U32;
    int b = blockIdx.z;
    int p0 = blockIdx.x * 128;
    int tid = threadIdx.x;
    int lane = tid & 31, w = tid >> 5;
    int wr = w >> 2, wc = w & 3;
    int g = lane >> 2, tg = lane & 3;
    const float* xb = x + (size_t)b * CINC * HWP;
    __half* ob = g_mid + (size_t)b * MIDC * HWP;

    // Prefetch A(0) and A(1) upfront (two commit groups)
    {
        const uint4* src = (const uint4*)g_WexpF;
        #pragma unroll
        for (int j = 0; j < 6; j++)
            cpa16(smaddr(As0) + (tid + j * 256) * 16, src + tid + j * 256, true);
        cpa_commit();
        src += EXP_A_U32 / 4;
        #pragma unroll
        for (int j = 0; j < 6; j++)
            cpa16(smaddr(As1) + (tid + j * 256) * 16, src + tid + j * 256, true);
        cpa_commit();
    }
    // Convert B (overlaps both A fetches)
    #pragma unroll
    for (int j = 0; j < 6; j++) {
        int v = tid + j * 256;
        int k2 = v >> 5, c4 = (v & 31) << 2;
        int p = p0 + c4;
        float4 r0 = make_float4(0.f, 0.f, 0.f, 0.f), r1 = r0;
        if (p < HWP) {
            r0 = *(const float4*)&xb[(size_t)(2 * k2) * HWP + p];
            r1 = *(const float4*)&xb[(size_t)(2 * k2 + 1) * HWP + p];
        }
        float e0[4] = {r0.x, r0.y, r0.z, r0.w};
        float e1[4] = {r1.x, r1.y, r1.z, r1.w};
        uint32_t hh[4], ll[4];
        #pragma unroll
        for (int i = 0; i < 4; i++) {
            float h0 = bf16hi(e0[i]), h1 = bf16hi(e1[i]);
            hh[i] = packbf2(h0, h1);
            ll[i] = packbf2(e0[i] - h0, e1[i] - h1);
        }
        *(uint4*)&Bh[k2 * BSS + c4] = make_uint4(hh[0], hh[1], hh[2], hh[3]);
        *(uint4*)&Bl[k2 * BSS + c4] = make_uint4(ll[0], ll[1], ll[2], ll[3]);
    }

    for (int mt = 0; mt < 3; mt++) {
        uint32_t* Acur = (mt & 1) ? As1 : As0;
        if (mt == 2) { cpa_wait<0>(); } else { cpa_wait<1>(); }
        __syncthreads();   // A(mt) visible; B visible (mt=0); prev buffer free

        float acc[2][4][4] = {};
        #pragma unroll
        for (int ki = 0; ki < 6; ki++) {
            uint4 ah[2], al[2];
            #pragma unroll
            for (int mi = 0; mi < 2; mi++) {
                int off = (((wr * 6 + ki) * 2 + mi) * 2) * 128 + lane * 4;
                ah[mi] = *(const uint4*)&Acur[off];
                al[mi] = *(const uint4*)&Acur[off + 128];
            }
            uint32_t bh[4][2], bl[4][2];
            int kr2 = ki * 8;
            #pragma unroll
            for (int ni = 0; ni < 4; ni++) {
                int nb = wc * 32 + ni * 8 + g;
                bh[ni][0] = Bh[(kr2 + tg) * BSS + nb];
                bh[ni][1] = Bh[(kr2 + tg + 4) * BSS + nb];
                bl[ni][0] = Bl[(kr2 + tg) * BSS + nb];
                bl[ni][1] = Bl[(kr2 + tg + 4) * BSS + nb];
            }
            #pragma unroll
            for (int mi = 0; mi < 2; mi++)
                #pragma unroll
                for (int ni = 0; ni < 4; ni++) {
                    mma16(acc[mi][ni], (const uint32_t*)&ah[mi], bh[ni]);
                    mma16(acc[mi][ni], (const uint32_t*)&al[mi], bh[ni]);
                    mma16(acc[mi][ni], (const uint32_t*)&ah[mi], bl[ni]);
                }
        }

        int m0 = mt * 64;
        #pragma unroll
        for (int mi = 0; mi < 2; mi++) {
            int o = m0 + wr * 32 + mi * 16 + g;
            float b0f = g_bexp[o], b1f = g_bexp[o + 8];
            #pragma unroll
            for (int ni = 0; ni < 4; ni++) {
                int p = p0 + wc * 32 + ni * 8 + tg * 2;
                if (p < HWP) {
                    *(__half2*)&ob[(size_t)o * HWP + p] =
                        __floats2half2_rn(silu_f(acc[mi][ni][0] + b0f),
                                          silu_f(acc[mi][ni][1] + b0f));
                    *(__half2*)&ob[(size_t)(o + 8) * HWP + p] =
                        __floats2half2_rn(silu_f(acc[mi][ni][2] + b1f),
                                          silu_f(acc[mi][ni][3] + b1f));
                }
            }
        }
        __syncthreads();   // all reads of Acur done before refill
        if (mt == 0) {
            const uint4* src = ((const uint4*)g_WexpF) + 2 * (EXP_A_U32 / 4);
            #pragma unroll
            for (int j = 0; j < 6; j++)
                cpa16(smaddr(As0) + (tid + j * 256) * 16, src + tid + j * 256, true);
            cpa_commit();
        }
    }
}

// ---------------------------------------------------------------------------
// dwmerge v4: border-only zeroing; single packed-fp16 output plane.
// ---------------------------------------------------------------------------
#define SROW 64
__global__ void __launch_bounds__(256) dwmerge_kernel() {
    __shared__ float sps[2][58 * SROW];
    __shared__ float sred[16];
    int bc = blockIdx.x;
    int b = bc / 96, k2 = bc - b * 96;
    int tid = threadIdx.x;

    int oyA[2], oxA[2];
    const __half* planes[2];
    float w9[2][9], T[2];
    #pragma unroll
    for (int ch = 0; ch < 2; ch++) {
        int c = 2 * k2 + ch;
        int cpre = (c & 3) * 48 + (c >> 2);
        int gg = c & 3;
        oyA[ch] = (gg == 0) ? -1 : (gg == 2) ? 1 : 0;
        oxA[ch] = (gg == 1) ? -1 : (gg == 3) ? 1 : 0;
        planes[ch] = g_mid + ((size_t)b * MIDC + cpre) * HWP;
        #pragma unroll
        for (int k = 0; k < 9; k++) w9[ch][k] = g_W9[c * 9 + k];
        T[ch] = g_T[c];
    }

    // Phase A: fill shifted rows + zero never-written borders (disjoint writes)
    for (int t = tid; t < 1624; t += 256) {
        int ch = t >= 812;
        int u = t - ch * 812;
        int r = u / 14, qq = u - r * 14;
        int hp = r - 1, hs = hp + oyA[ch];
        if ((unsigned)hp < 56u && (unsigned)hs < 56u) {
            uint2 v = *(const uint2*)&planes[ch][hs * 56 + qq * 4];
            float2 f01 = __half22float2(*(__half2*)&v.x);
            float2 f23 = __half22float2(*(__half2*)&v.y);
            float* d = &sps[ch][r * SROW + qq * 4 + (5 - oxA[ch])];
            d[0] = f01.x; d[1] = f01.y; d[2] = f23.x; d[3] = f23.y;
        }
    }
    for (int t = tid; t < 2 * 3 * 16; t += 256) {
        int ch = t >= 48;
        int u = t - ch * 48;
        int slot = u >> 4, c4 = (u & 15) << 2;
        int oy = oyA[ch];
        int rr = (slot == 0) ? 0 : (slot == 1) ? 57
                : (oy == -1) ? 1 : (oy == 1) ? 56 : 0;
        *(float4*)&sps[ch][rr * SROW + c4] = make_float4(0.f, 0.f, 0.f, 0.f);
    }
    for (int t = tid; t < 2 * 2 * 58; t += 256) {
        int ch = t >= 116;
        int u = t - ch * 116;
        int which = u >= 58;
        int rr = u - which * 58;
        int ox = oxA[ch];
        int cc = (ox == 0) ? (which ? 61 : 4)
               : (ox == 1) ? (which ? 61 : 60)
                           : (which ? 5 : 4);
        sps[ch][rr * SROW + cc] = 0.f;
    }
    __syncthreads();

    // Pad-cell fix (cells the shifted copy DID fill but conv-pad must zero)
    if (tid < 116) {
        int ch = tid >= 58;
        int r = tid - ch * 58;
        int ox = oxA[ch];
        if (ox == 1)  sps[ch][r * SROW + 4] = 0.f;
        if (ox == -1) sps[ch][r * SROW + 61] = 0.f;
    }
    __syncthreads();

    uint32_t* oF = g_mergedF + ((size_t)b * 96 + k2) * HWP;
    float ls0 = 0.f, ls1 = 0.f;

    for (int t = tid; t < 784; t += 256) {
        int h = t / 14, q = t - h * 14;
        float a0[4] = {T[0], T[0], T[0], T[0]};
        float a1[4] = {T[1], T[1], T[1], T[1]};
        #pragma unroll
        for (int ch = 0; ch < 2; ch++) {
            float* accp = ch ? a1 : a0;
            #pragma unroll
            for (int dy = 0; dy < 3; dy++) {
                const float* row = &sps[ch][(h + dy) * SROW + q * 4 + 4];
                float4 A = *(const float4*)row;
                float2 Bv = *(const float2*)(row + 4);
                float wA = w9[ch][dy * 3], wB = w9[ch][dy * 3 + 1], wC = w9[ch][dy * 3 + 2];
                accp[0] += wA * A.x + wB * A.y + wC * A.z;
                accp[1] += wA * A.y + wB * A.z + wC * A.w;
                accp[2] += wA * A.z + wB * A.w + wC * Bv.x;
                accp[3] += wA * A.w + wB * Bv.x + wC * Bv.y;
            }
        }
        uint32_t Fw[4];
        #pragma unroll
        for (int i = 0; i < 4; i++) {
            float s0 = silu_f(a0[i]);
            float s1 = silu_f(a1[i]);
            Fw[i] = packfp2(s0, s1);
            ls0 += s0;
            ls1 += s1;
        }
        int o = h * 56 + q * 4;
        *(uint4*)&oF[o] = make_uint4(Fw[0], Fw[1], Fw[2], Fw[3]);
    }

    int wid = tid >> 5, lane = tid & 31;
    #pragma unroll
    for (int o = 16; o > 0; o >>= 1) {
        ls0 += __shfl_down_sync(0xffffffffu, ls0, o);
        ls1 += __shfl_down_sync(0xffffffffu, ls1, o);
    }
    if (lane == 0) { sred[wid] = ls0; sred[8 + wid] = ls1; }
    __syncthreads();
    if (tid < 16) {
        float v = sred[tid];
        #pragma unroll
        for (int o = 4; o > 0; o >>= 1) v += __shfl_down_sync(0xffffu, v, o);
        if (tid == 0) g_sums[b * 192 + 2 * k2] = v;
        if (tid == 8) g_sums[b * 192 + 2 * k2 + 1] = v;
    }
}

// ---------------------------------------------------------------------------
// SE gating + per-batch scaled proj weights, re-split to fp16 hi/lo.
// ---------------------------------------------------------------------------
__global__ void __launch_bounds__(256) se_scale_kernel(const float* __restrict__ red_w,
                                                       const float* __restrict__ red_b,
                                                       const float* __restrict__ exp_w,
                                                       const float* __restrict__ exp_b) {
    __shared__ float smean[192];
    __shared__ float sredu[24];
    __shared__ float s_se[192];
    int b = blockIdx.x, cc = blockIdx.y;
    int tid = threadIdx.x;

    if (tid < 192) smean[tid] = g_sums[b * 192 + tid] * (1.f / 3136.f);
    __syncthreads();
    if (tid < 24) {
        int gq = tid >> 1;
        float a = red_b[tid];
        #pragma unroll
        for (int i = 0; i < 16; i++) a += red_w[tid * 16 + i] * smean[gq * 16 + i];
        sredu[tid] = fmaxf(a, 0.f);
    }
    __syncthreads();
    if (tid < 192) {
        int gq = tid >> 4;
        float v = exp_w[tid * 2] * sredu[gq * 2] + exp_w[tid * 2 + 1] * sredu[gq * 2 + 1]
                + exp_b[tid];
        s_se[tid] = 1.f / (1.f + __expf(-v));
    }
    __syncthreads();

    uint32_t* dstb = g_WprojSE + (size_t)b * 18432;
    const uint4* src = ((const uint4*)g_WprojF) + cc * (PROJ_A_U32 / 4);
    uint4* dst = ((uint4*)dstb) + cc * (PROJ_A_U32 / 4);
    for (int i = tid; i < 576; i += 256) {
        int grp = i >> 5, li = i & 31;
        int ki = (grp / 3) % 3;
        uint4 H = src[grp * 64 + li];
        uint4 L = src[grp * 64 + li + 32];
        int k2a = cc * 24 + ki * 8 + (li & 3);
        float se0 = s_se[2 * k2a], se1 = s_se[2 * k2a + 1];
        float se2 = s_se[2 * k2a + 8], se3 = s_se[2 * k2a + 9];
        uint32_t hu[4] = {H.x, H.y, H.z, H.w};
        uint32_t lu[4] = {L.x, L.y, L.z, L.w};
        uint32_t nh[4], nl[4];
        #pragma unroll
        for (int q = 0; q < 4; q++) {
            float sA = (q < 2) ? se0 : se2;
            float sB = (q < 2) ? se1 : se3;
            float2 hf = unpackbf2(hu[q]);
            float2 lf = unpackbf2(lu[q]);
            float v0 = (hf.x + lf.x) * sA;
            float v1 = (hf.y + lf.y) * sB;
            float h0 = fp16hi(v0), h1 = fp16hi(v1);
            nh[q] = packfp2(h0, h1);
            nl[q] = packfp2(v0 - h0, v1 - h1);
        }
        dst[grp * 64 + li]      = make_uint4(nh[0], nh[1], nh[2], nh[3]);
        dst[grp * 64 + li + 32] = make_uint4(nl[0], nl[1], nl[2], nl[3]);
    }
}

// ---------------------------------------------------------------------------
// Project 1x1 GEMM. M=96 x N=128; 4 k-chunks of 48; depth-2 cp.async;
// fp16 single-plane B, fp16 hi/lo A (2 MMAs per fragment).
// x rows 0..60 prefetched into freed smem during last chunk.
// ---------------------------------------------------------------------------
__global__ void __launch_bounds__(256, 2) proj_gemm(const float* __restrict__ x,
                                                    float* __restrict__ out) {
    extern __shared__ uint32_t smu[];
    uint32_t* As0 = smu;                        // PROJ_A_U32
    uint32_t* As1 = smu + PROJ_A_U32;
    uint32_t* Bst = smu + 2 * PROJ_A_U32;       // 2 stages x PROJ_B_U32

    int b = blockIdx.z;
    int p0 = blockIdx.x * 128;
    int tid = threadIdx.x;
    int lane = tid & 31, w = tid >> 5;
    int wr = w >> 2, wc = w & 3;
    int g = lane >> 2, tg = lane & 3;
    const uint32_t* mF = g_mergedF + (size_t)b * 96 * HWP;
    const uint4* Asrc = (const uint4*)(g_WprojSE + (size_t)b * 18432);
    const float* xb = x + (size_t)b * COUTC * HWP;

    auto cp_stage = [&](int c) {
        int stage = c & 1;
        uint32_t dstB = smaddr(Bst) + stage * PROJ_B_U32 * 4;
        const uint4* sF = (const uint4*)(mF + (size_t)(c * 24) * HWP);
        #pragma unroll
        for (int j = 0; j < 3; j++) {
            int v = tid + j * 256;
            int r = v >> 5, c4 = (v & 31);
            int p = p0 + c4 * 4;
            bool ok = p < HWP;                  // zero-fill pad (intended)
            size_t so = (size_t)r * (HWP / 4) + (p0 >> 2) + c4;
            cpa16(dstB + (r * BSS + c4 * 4) * 4, sF + (ok ? so : 0), ok);
        }
        // A chunk: 1152 uint4 = 4*256 + 128 exact
        uint32_t dstA = smaddr(stage ? As1 : As0);
        const uint4* sA = Asrc + c * (PROJ_A_U32 / 4);
        #pragma unroll
        for (int j = 0; j < 4; j++) {
            int v = tid + j * 256;
            cpa16(dstA + v * 16, sA + v, true);
        }
        if (tid < 128) {
            int v = tid + 1024;
            cpa16(dstA + v * 16, sA + v, true);
        }
        cpa_commit();
    };
    cp_stage(0);
    cp_stage(1);

    float acc[3][4][4] = {};

    for (int c = 0; c < 4; c++) {
        uint32_t* Acur = (c & 1) ? As1 : As0;
        uint32_t* BfS = Bst + (c & 1) * PROJ_B_U32;
        cpa_wait<1>();        // chunk c complete (FIFO); c+1 may be in flight
        __syncthreads();

        #pragma unroll
        for (int ki = 0; ki < 3; ki++) {
            uint4 ah[3], al[3];
            #pragma unroll
            for (int mi = 0; mi < 3; mi++) {
                int off = ((wr * 3 + ki) * 3 + mi) * 256 + lane * 4;
                ah[mi] = *(const uint4*)&Acur[off];
                al[mi] = *(const uint4*)&Acur[off + 128];
            }
            uint32_t bf[4][2];
            int kr2 = ki * 8;
            #pragma unroll
            for (int ni = 0; ni < 4; ni++) {
                int nb = wc * 32 + ni * 8 + g;
                bf[ni][0] = BfS[(kr2 + tg) * BSS + nb];
                bf[ni][1] = BfS[(kr2 + tg + 4) * BSS + nb];
            }
            #pragma unroll
            for (int mi = 0; mi < 3; mi++)
                #pragma unroll
                for (int ni = 0; ni < 4; ni++) {
                    mma16f(acc[mi][ni], (const uint32_t*)&ah[mi], bf[ni]);
                    mma16f(acc[mi][ni], (const uint32_t*)&al[mi], bf[ni]);
                }
        }
        __syncthreads();      // buffer (c&1) now free for refill

        if (c < 2) {
            cp_stage(c + 2);
        } else if (c == 2) {
            // Prefetch x rows 0..60 into As0 (36 rows) + Bst stage0 (25 rows)
            #pragma unroll
            for (int j = 0; j < 8; j++) {
                int t = tid + j * 256;
                if (t < 1952) {
                    int row = t >> 5, c4 = t & 31;
                    int p = p0 + c4 * 4;
                    int idx = row * 128 + c4 * 4;               // u32 index
                    uint32_t off = (idx < PROJ_A_U32) ? (uint32_t)idx
                                                      : (uint32_t)(idx + PROJ_A_U32);
                    cpa16(smaddr(smu) + off * 4,
                          xb + (size_t)row * HWP + p, p < HWP);
                }
            }
            cpa_commit();
        }
    }
    cpa_wait<0>();   // x prefetch complete
    __syncthreads();

    float* ob = out + (size_t)b * COUTC * HWP;
    #pragma unroll
    for (int mi = 0; mi < 3; mi++) {
        int o = wr * 48 + mi * 16 + g;
        float b0f = g_bproj[o], b1f = g_bproj[o + 8];
        #pragma unroll
        for (int ni = 0; ni < 4; ni++) {
            int pp = wc * 32 + ni * 8 + tg * 2;
            int p = p0 + pp;
            if (p < HWP) {
                float2 x0, x1;
                {
                    int idx = o * 128 + pp;
                    uint32_t off = (idx < PROJ_A_U32) ? (uint32_t)idx
                                                      : (uint32_t)(idx + PROJ_A_U32);
                    x0 = (o < 61) ? make_float2(__uint_as_float(smu[off]),
                                                __uint_as_float(smu[off + 1]))
                                  : *(const float2*)&xb[(size_t)o * HWP + p];
                }
                {
                    int o2 = o + 8;
                    int idx = o2 * 128 + pp;
                    uint32_t off = (idx < PROJ_A_U32) ? (uint32_t)idx
                                                      : (uint32_t)(idx + PROJ_A_U32);
                    x1 = (o2 < 61) ? make_float2(__uint_as_float(smu[off]),
                                                 __uint_as_float(smu[off + 1]))
                                   : *(const float2*)&xb[(size_t)(o + 8) * HWP + p];
                }
                float2 r0;
                r0.x = silu_f(acc[mi][ni][0] + b0f + x0.x);
                r0.y = silu_f(acc[mi][ni][1] + b0f + x0.y);
                *(float2*)&ob[(size_t)o * HWP + p] = r0;
                float2 r1;
                r1.x = silu_f(acc[mi][ni][2] + b1f + x1.x);
                r1.y = silu_f(acc[mi][ni][3] + b1f + x1.y);
                *(float2*)&ob[(size_t)(o + 8) * HWP + p] = r1;
            }
        }
    }
}

// ---------------------------------------------------------------------------
extern "C" void kernel_launch(void* const* d_in, const int* in_sizes, int n_in,
                              void* d_out, int out_size) {
    const float* x         = (const float*)d_in[0];
    const float* expand_w  = (const float*)d_in[1];
    const float* expand_bn = (const float*)d_in[2];
    const float* dw_w      = (const float*)d_in[3];
    const float* dw_bn     = (const float*)d_in[4];
    const float* id_w      = (const float*)d_in[5];
    const float* id_bn     = (const float*)d_in[6];
    const float* merge_bn  = (const float*)d_in[7];
    const float* se_red_w  = (const float*)d_in[8];
    const float* se_red_b  = (const float*)d_in[9];
    const float* se_exp_w  = (const float*)d_in[10];
    const float* se_exp_b  = (const float*)d_in[11];
    const float* proj_w    = (const float*)d_in[12];
    const float* proj_bn   = (const float*)d_in[13];
    float* out = (float*)d_out;

    cudaFuncSetAttribute(expand_gemm, cudaFuncAttributeMaxDynamicSharedMemorySize, EXP_SMEM);
    cudaFuncSetAttribute(proj_gemm,   cudaFuncAttributeMaxDynamicSharedMemorySize, PROJ_SMEM);

    prep_kernel<<<264, 256>>>(expand_w, expand_bn, dw_w, dw_bn, id_w, id_bn,
                              merge_bn, proj_w, proj_bn);
    expand_gemm<<<dim3(25, 1, BZ), 256, EXP_SMEM>>>(x);
    dwmerge_kernel<<<BZ * 96, 256>>>();
    se_scale_kernel<<<dim3(BZ, 4), 256>>>(se_red_w, se_red_b, se_exp_w, se_exp_b);
    proj_gemm<<<dim3(25, 1, BZ), 256, PROJ_SMEM>>>(x, out);
}

// round 16
// speedup vs baseline: 1.4253x; 1.0452x over previous
#include <cuda_runtime.h>
#include <cuda_bf16.h>
#include <cuda_fp16.h>
#include <math.h>
#include <stdint.h>

#define BZ    64
#define CINC  96
#define COUTC 96
#define MIDC  192
#define HWP   3136
#define EPSBN 1e-5f

#define BSS 136                    // pair-row stride (u32): bank = 8*tg+g, conflict-free
#define EXP_A_U32   6144           // per-mt A chunk  [wr2][ki6][mi2][hl2][lane32][q4]
#define PROJ_A_U32  4608           // per-kchunk A    [wr2][ki3][mi3][hl2][lane32][q4]
#define EXP_B_U32   (48 * BSS)     // single fp16 plane, 48 pair-rows
#define PROJ_B_U32  (24 * BSS)     // single fp16 plane per chunk, 24 pair-rows
#define EXP_SMEM  ((2 * EXP_A_U32 + EXP_B_U32) * 4)          // 75264 B
#define PROJ_SMEM ((2 * PROJ_A_U32 + 2 * PROJ_B_U32) * 4)    // 62976 B

// Scratch (device globals: allowed; no cudaMalloc anywhere)
__device__ __align__(16) __half   g_mid[(size_t)BZ * MIDC * HWP];    // fp16 mid
__device__ __align__(16) uint32_t g_mergedF[(size_t)BZ * 96 * HWP];  // packed fp16 (c,c+1)
__device__ float    g_sums[BZ * MIDC];
__device__ __align__(16) uint32_t g_WexpF[18432];   // fp16 hi/lo fragment order
__device__ __align__(16) uint32_t g_WprojF[18432];  // bf16 hi/lo fragment order
__device__ __align__(16) uint32_t g_WprojSE[(size_t)BZ * 18432];  // per-batch SE-scaled fp16 hi/lo
__device__ float    g_bexp[MIDC];
__device__ float    g_W9[MIDC * 9];
__device__ float    g_T[MIDC];
__device__ float    g_bproj[COUTC];

__device__ __forceinline__ float silu_f(float v) { return v / (1.f + __expf(-v)); }

__device__ __forceinline__ uint32_t packbf2(float lo_elem, float hi_elem) {
    __nv_bfloat162 t = __floats2bfloat162_rn(lo_elem, hi_elem);  // .x = low 16 bits
    return *(uint32_t*)&t;
}
__device__ __forceinline__ uint32_t packfp2(float lo_elem, float hi_elem) {
    __half2 t = __floats2half2_rn(lo_elem, hi_elem);             // .x = low 16 bits
    return *(uint32_t*)&t;
}
__device__ __forceinline__ float2 unpackbf2(uint32_t u) {
    __nv_bfloat162 t = *(__nv_bfloat162*)&u;
    return __bfloat1622float2(t);
}
__device__ __forceinline__ float bf16hi(float v) {
    return __bfloat162float(__float2bfloat16_rn(v));
}
__device__ __forceinline__ float fp16hi(float v) {
    return __half2float(__float2half_rn(v));
}

__device__ __forceinline__ void mma16f(float* c, const uint32_t* a, const uint32_t* b) {
    asm volatile(
        "mma.sync.aligned.m16n8k16.row.col.f32.f16.f16.f32 "
        "{%0,%1,%2,%3},{%4,%5,%6,%7},{%8,%9},{%0,%1,%2,%3};"
        : "+f"(c[0]), "+f"(c[1]), "+f"(c[2]), "+f"(c[3])
        : "r"(a[0]), "r"(a[1]), "r"(a[2]), "r"(a[3]), "r"(b[0]), "r"(b[1]));
}

__device__ __forceinline__ uint32_t smaddr(const void* p) {
    return (uint32_t)__cvta_generic_to_shared(p);
}
__device__ __forceinline__ void cpa16(uint32_t dst_s, const void* src, bool valid) {
    // NOTE: valid=false still WRITES 16 zero bytes to dst (zero-fill).
    int sz = valid ? 16 : 0;
    asm volatile("cp.async.cg.shared.global [%0], [%1], 16, %2;\n"
                 :: "r"(dst_s), "l"(src), "r"(sz));
}
__device__ __forceinline__ void cpa_commit() {
    asm volatile("cp.async.commit_group;\n");
}
template <int N>
__device__ __forceinline__ void cpa_wait() {
    asm volatile("cp.async.wait_group %0;\n" :: "n"(N));
}

// ---------------------------------------------------------------------------
// prep: fold BN; emit fragment-ordered weights (expand: fp16 hi/lo;
// proj: bf16 hi/lo, re-split to fp16 after SE scaling).
// ---------------------------------------------------------------------------
__global__ void prep_kernel(const float* __restrict__ expand_w,
                            const float* __restrict__ expand_bn,
                            const float* __restrict__ dw_w,
                            const float* __restrict__ dw_bn,
                            const float* __restrict__ id_w,
                            const float* __restrict__ id_bn,
                            const float* __restrict__ merge_bn,
                            const float* __restrict__ proj_w,
                            const float* __restrict__ proj_bn) {
    int tid = blockIdx.x * blockDim.x + threadIdx.x;
    int nth = gridDim.x * blockDim.x;

    for (int idx = tid; idx < 18432; idx += nth) {
        int q = idx & 3, lane = (idx >> 2) & 31, hl = (idx >> 7) & 1;
        int t = idx >> 8;
        int mi = t & 1; t >>= 1;
        int ki = t % 6; t /= 6;
        int wr = t & 1; t >>= 1;
        int mt = t;
        int m = mt * 64 + wr * 32 + mi * 16 + (lane >> 2) + 8 * (q & 1);
        int k = ki * 16 + (lane & 3) * 2 + 8 * (q >> 1);
        float sc = expand_bn[m] * rsqrtf(expand_bn[3 * MIDC + m] + EPSBN);
        float w0 = expand_w[m * CINC + k] * sc;
        float w1 = expand_w[m * CINC + k + 1] * sc;
        float h0 = fp16hi(w0), h1 = fp16hi(w1);
        g_WexpF[idx] = hl ? packfp2(w0 - h0, w1 - h1) : packfp2(h0, h1);
    }
    for (int idx = tid; idx < 18432; idx += nth) {
        int q = idx & 3, lane = (idx >> 2) & 31, hl = (idx >> 7) & 1;
        int t = idx >> 8;
        int mi = t % 3; t /= 3;
        int ki = t % 3; t /= 3;
        int wr = t & 1; int chunk = t >> 1;
        int m = wr * 48 + mi * 16 + (lane >> 2) + 8 * (q & 1);
        int k = chunk * 48 + ki * 16 + (lane & 3) * 2 + 8 * (q >> 1);
        float sc = proj_bn[m] * rsqrtf(proj_bn[3 * COUTC + m] + EPSBN);
        float w0 = proj_w[m * MIDC + k] * sc;
        float w1 = proj_w[m * MIDC + k + 1] * sc;
        float h0 = bf16hi(w0), h1 = bf16hi(w1);
        g_WprojF[idx] = hl ? packbf2(w0 - h0, w1 - h1) : packbf2(h0, h1);
    }
    for (int o = tid; o < MIDC; o += nth) {
        float sc = expand_bn[o] * rsqrtf(expand_bn[3 * MIDC + o] + EPSBN);
        g_bexp[o] = expand_bn[MIDC + o] - expand_bn[2 * MIDC + o] * sc;
    }
    for (int c = tid; c < MIDC; c += nth) {
        float dsc = dw_bn[c] * rsqrtf(dw_bn[3 * MIDC + c] + EPSBN);
        float dsh = dw_bn[MIDC + c] - dw_bn[2 * MIDC + c] * dsc;
        float isc = id_bn[c] * rsqrtf(id_bn[3 * MIDC + c] + EPSBN);
        float ish = id_bn[MIDC + c] - id_bn[2 * MIDC + c] * isc;
        float msc = merge_bn[c] * rsqrtf(merge_bn[3 * MIDC + c] + EPSBN);
        float msh = merge_bn[MIDC + c] - merge_bn[2 * MIDC + c] * msc;
        #pragma unroll
        for (int k = 0; k < 9; k++) g_W9[c * 9 + k] = msc * dsc * dw_w[c * 9 + k];
        g_W9[c * 9 + 4] += msc * isc * id_w[c];
        g_T[c] = msc * (dsh + ish) + msh;
    }
    for (int o = tid; o < COUTC; o += nth) {
        float sc = proj_bn[o] * rsqrtf(proj_bn[3 * COUTC + o] + EPSBN);
        g_bproj[o] = proj_bn[COUTC + o] - proj_bn[2 * COUTC + o] * sc;
    }
}

// ---------------------------------------------------------------------------
// Expand 1x1 GEMM. 192(Mx3 passes) x 128(N); warp tile 32x32; fp16 mma.
// A fp16 hi/lo via depth-2 cp.async; B = single fp16 plane converted once.
// fp16 output.
// ---------------------------------------------------------------------------
__global__ void __launch_bounds__(256, 2) expand_gemm(const float* __restrict__ x) {
    extern __shared__ uint32_t smu[];
    uint32_t* As0 = smu;                    // EXP_A_U32
    uint32_t* As1 = smu + EXP_A_U32;
    uint32_t* Bf  = smu + 2 * EXP_A_U32;    // EXP_B_U32 (single plane)
    int b = blockIdx.z;
    int p0 = blockIdx.x * 128;
    int tid = threadIdx.x;
    int lane = tid & 31, w = tid >> 5;
    int wr = w >> 2, wc = w & 3;
    int g = lane >> 2, tg = lane & 3;
    const float* xb = x + (size_t)b * CINC * HWP;
    __half* ob = g_mid + (size_t)b * MIDC * HWP;

    // Prefetch A(0) and A(1) upfront (two commit groups)
    {
        const uint4* src = (const uint4*)g_WexpF;
        #pragma unroll
        for (int j = 0; j < 6; j++)
            cpa16(smaddr(As0) + (tid + j * 256) * 16, src + tid + j * 256, true);
        cpa_commit();
        src += EXP_A_U32 / 4;
        #pragma unroll
        for (int j = 0; j < 6; j++)
            cpa16(smaddr(As1) + (tid + j * 256) * 16, src + tid + j * 256, true);
        cpa_commit();
    }
    // Convert B to single fp16 plane (overlaps both A fetches)
    #pragma unroll
    for (int j = 0; j < 6; j++) {
        int v = tid + j * 256;
        int k2 = v >> 5, c4 = (v & 31) << 2;
        int p = p0 + c4;
        float4 r0 = make_float4(0.f, 0.f, 0.f, 0.f), r1 = r0;
        if (p < HWP) {
            r0 = *(const float4*)&xb[(size_t)(2 * k2) * HWP + p];
            r1 = *(const float4*)&xb[(size_t)(2 * k2 + 1) * HWP + p];
        }
        uint4 t;
        t.x = packfp2(r0.x, r1.x);
        t.y = packfp2(r0.y, r1.y);
        t.z = packfp2(r0.z, r1.z);
        t.w = packfp2(r0.w, r1.w);
        *(uint4*)&Bf[k2 * BSS + c4] = t;
    }

    for (int mt = 0; mt < 3; mt++) {
        uint32_t* Acur = (mt & 1) ? As1 : As0;
        if (mt == 2) { cpa_wait<0>(); } else { cpa_wait<1>(); }
        __syncthreads();   // A(mt) visible; B visible (mt=0); prev buffer free

        float acc[2][4][4] = {};
        #pragma unroll
        for (int ki = 0; ki < 6; ki++) {
            uint4 ah[2], al[2];
            #pragma unroll
            for (int mi = 0; mi < 2; mi++) {
                int off = (((wr * 6 + ki) * 2 + mi) * 2) * 128 + lane * 4;
                ah[mi] = *(const uint4*)&Acur[off];
                al[mi] = *(const uint4*)&Acur[off + 128];
            }
            uint32_t bf[4][2];
            int kr2 = ki * 8;
            #pragma unroll
            for (int ni = 0; ni < 4; ni++) {
                int nb = wc * 32 + ni * 8 + g;
                bf[ni][0] = Bf[(kr2 + tg) * BSS + nb];
                bf[ni][1] = Bf[(kr2 + tg + 4) * BSS + nb];
            }
            #pragma unroll
            for (int mi = 0; mi < 2; mi++)
                #pragma unroll
                for (int ni = 0; ni < 4; ni++) {
                    mma16f(acc[mi][ni], (const uint32_t*)&ah[mi], bf[ni]);
                    mma16f(acc[mi][ni], (const uint32_t*)&al[mi], bf[ni]);
                }
        }

        int m0 = mt * 64;
        #pragma unroll
        for (int mi = 0; mi < 2; mi++) {
            int o = m0 + wr * 32 + mi * 16 + g;
            float b0f = g_bexp[o], b1f = g_bexp[o + 8];
            #pragma unroll
            for (int ni = 0; ni < 4; ni++) {
                int p = p0 + wc * 32 + ni * 8 + tg * 2;
                if (p < HWP) {
                    *(__half2*)&ob[(size_t)o * HWP + p] =
                        __floats2half2_rn(silu_f(acc[mi][ni][0] + b0f),
                                          silu_f(acc[mi][ni][1] + b0f));
                    *(__half2*)&ob[(size_t)(o + 8) * HWP + p] =
                        __floats2half2_rn(silu_f(acc[mi][ni][2] + b1f),
                                          silu_f(acc[mi][ni][3] + b1f));
                }
            }
        }
        __syncthreads();   // all reads of Acur done before refill
        if (mt == 0) {
            const uint4* src = ((const uint4*)g_WexpF) + 2 * (EXP_A_U32 / 4);
            #pragma unroll
            for (int j = 0; j < 6; j++)
                cpa16(smaddr(As0) + (tid + j * 256) * 16, src + tid + j * 256, true);
            cpa_commit();
        }
    }
}

// ---------------------------------------------------------------------------
// dwmerge v4: border-only zeroing; single packed-fp16 output plane.
// ---------------------------------------------------------------------------
#define SROW 64
__global__ void __launch_bounds__(256) dwmerge_kernel() {
    __shared__ float sps[2][58 * SROW];
    __shared__ float sred[16];
    int bc = blockIdx.x;
    int b = bc / 96, k2 = bc - b * 96;
    int tid = threadIdx.x;

    int oyA[2], oxA[2];
    const __half* planes[2];
    float w9[2][9], T[2];
    #pragma unroll
    for (int ch = 0; ch < 2; ch++) {
        int c = 2 * k2 + ch;
        int cpre = (c & 3) * 48 + (c >> 2);
        int gg = c & 3;
        oyA[ch] = (gg == 0) ? -1 : (gg == 2) ? 1 : 0;
        oxA[ch] = (gg == 1) ? -1 : (gg == 3) ? 1 : 0;
        planes[ch] = g_mid + ((size_t)b * MIDC + cpre) * HWP;
        #pragma unroll
        for (int k = 0; k < 9; k++) w9[ch][k] = g_W9[c * 9 + k];
        T[ch] = g_T[c];
    }

    // Phase A: fill shifted rows + zero never-written borders (disjoint writes)
    for (int t = tid; t < 1624; t += 256) {
        int ch = t >= 812;
        int u = t - ch * 812;
        int r = u / 14, qq = u - r * 14;
        int hp = r - 1, hs = hp + oyA[ch];
        if ((unsigned)hp < 56u && (unsigned)hs < 56u) {
            uint2 v = *(const uint2*)&planes[ch][hs * 56 + qq * 4];
            float2 f01 = __half22float2(*(__half2*)&v.x);
            float2 f23 = __half22float2(*(__half2*)&v.y);
            float* d = &sps[ch][r * SROW + qq * 4 + (5 - oxA[ch])];
            d[0] = f01.x; d[1] = f01.y; d[2] = f23.x; d[3] = f23.y;
        }
    }
    for (int t = tid; t < 2 * 3 * 16; t += 256) {
        int ch = t >= 48;
        int u = t - ch * 48;
        int slot = u >> 4, c4 = (u & 15) << 2;
        int oy = oyA[ch];
        int rr = (slot == 0) ? 0 : (slot == 1) ? 57
                : (oy == -1) ? 1 : (oy == 1) ? 56 : 0;
        *(float4*)&sps[ch][rr * SROW + c4] = make_float4(0.f, 0.f, 0.f, 0.f);
    }
    for (int t = tid; t < 2 * 2 * 58; t += 256) {
        int ch = t >= 116;
        int u = t - ch * 116;
        int which = u >= 58;
        int rr = u - which * 58;
        int ox = oxA[ch];
        int cc = (ox == 0) ? (which ? 61 : 4)
               : (ox == 1) ? (which ? 61 : 60)
                           : (which ? 5 : 4);
        sps[ch][rr * SROW + cc] = 0.f;
    }
    __syncthreads();

    // Pad-cell fix
    if (tid < 116) {
        int ch = tid >= 58;
        int r = tid - ch * 58;
        int ox = oxA[ch];
        if (ox == 1)  sps[ch][r * SROW + 4] = 0.f;
        if (ox == -1) sps[ch][r * SROW + 61] = 0.f;
    }
    __syncthreads();

    uint32_t* oF = g_mergedF + ((size_t)b * 96 + k2) * HWP;
    float ls0 = 0.f, ls1 = 0.f;

    for (int t = tid; t < 784; t += 256) {
        int h = t / 14, q = t - h * 14;
        float a0[4] = {T[0], T[0], T[0], T[0]};
        float a1[4] = {T[1], T[1], T[1], T[1]};
        #pragma unroll
        for (int ch = 0; ch < 2; ch++) {
            float* accp = ch ? a1 : a0;
            #pragma unroll
            for (int dy = 0; dy < 3; dy++) {
                const float* row = &sps[ch][(h + dy) * SROW + q * 4 + 4];
                float4 A = *(const float4*)row;
                float2 Bv = *(const float2*)(row + 4);
                float wA = w9[ch][dy * 3], wB = w9[ch][dy * 3 + 1], wC = w9[ch][dy * 3 + 2];
                accp[0] += wA * A.x + wB * A.y + wC * A.z;
                accp[1] += wA * A.y + wB * A.z + wC * A.w;
                accp[2] += wA * A.z + wB * A.w + wC * Bv.x;
                accp[3] += wA * A.w + wB * Bv.x + wC * Bv.y;
            }
        }
        uint32_t Fw[4];
        #pragma unroll
        for (int i = 0; i < 4; i++) {
            float s0 = silu_f(a0[i]);
            float s1 = silu_f(a1[i]);
            Fw[i] = packfp2(s0, s1);
            ls0 += s0;
            ls1 += s1;
        }
        int o = h * 56 + q * 4;
        *(uint4*)&oF[o] = make_uint4(Fw[0], Fw[1], Fw[2], Fw[3]);
    }

    int wid = tid >> 5, lane = tid & 31;
    #pragma unroll
    for (int o = 16; o > 0; o >>= 1) {
        ls0 += __shfl_down_sync(0xffffffffu, ls0, o);
        ls1 += __shfl_down_sync(0xffffffffu, ls1, o);
    }
    if (lane == 0) { sred[wid] = ls0; sred[8 + wid] = ls1; }
    __syncthreads();
    if (tid < 16) {
        float v = sred[tid];
        #pragma unroll
        for (int o = 4; o > 0; o >>= 1) v += __shfl_down_sync(0xffffu, v, o);
        if (tid == 0) g_sums[b * 192 + 2 * k2] = v;
        if (tid == 8) g_sums[b * 192 + 2 * k2 + 1] = v;
    }
}

// ---------------------------------------------------------------------------
// SE gating + per-batch scaled proj weights, re-split to fp16 hi/lo.
// ---------------------------------------------------------------------------
__global__ void __launch_bounds__(256) se_scale_kernel(const float* __restrict__ red_w,
                                                       const float* __restrict__ red_b,
                                                       const float* __restrict__ exp_w,
                                                       const float* __restrict__ exp_b) {
    __shared__ float smean[192];
    __shared__ float sredu[24];
    __shared__ float s_se[192];
    int b = blockIdx.x, cc = blockIdx.y;
    int tid = threadIdx.x;

    if (tid < 192) smean[tid] = g_sums[b * 192 + tid] * (1.f / 3136.f);
    __syncthreads();
    if (tid < 24) {
        int gq = tid >> 1;
        float a = red_b[tid];
        #pragma unroll
        for (int i = 0; i < 16; i++) a += red_w[tid * 16 + i] * smean[gq * 16 + i];
        sredu[tid] = fmaxf(a, 0.f);
    }
    __syncthreads();
    if (tid < 192) {
        int gq = tid >> 4;
        float v = exp_w[tid * 2] * sredu[gq * 2] + exp_w[tid * 2 + 1] * sredu[gq * 2 + 1]
                + exp_b[tid];
        s_se[tid] = 1.f / (1.f + __expf(-v));
    }
    __syncthreads();

    uint32_t* dstb = g_WprojSE + (size_t)b * 18432;
    const uint4* src = ((const uint4*)g_WprojF) + cc * (PROJ_A_U32 / 4);
    uint4* dst = ((uint4*)dstb) + cc * (PROJ_A_U32 / 4);
    for (int i = tid; i < 576; i += 256) {
        int grp = i >> 5, li = i & 31;
        int ki = (grp / 3) % 3;
        uint4 H = src[grp * 64 + li];
        uint4 L = src[grp * 64 + li + 32];
        int k2a = cc * 24 + ki * 8 + (li & 3);
        float se0 = s_se[2 * k2a], se1 = s_se[2 * k2a + 1];
        float se2 = s_se[2 * k2a + 8], se3 = s_se[2 * k2a + 9];
        uint32_t hu[4] = {H.x, H.y, H.z, H.w};
        uint32_t lu[4] = {L.x, L.y, L.z, L.w};
        uint32_t nh[4], nl[4];
        #pragma unroll
        for (int q = 0; q < 4; q++) {
            float sA = (q < 2) ? se0 : se2;
            float sB = (q < 2) ? se1 : se3;
            float2 hf = unpackbf2(hu[q]);
            float2 lf = unpackbf2(lu[q]);
            float v0 = (hf.x + lf.x) * sA;
            float v1 = (hf.y + lf.y) * sB;
            float h0 = fp16hi(v0), h1 = fp16hi(v1);
            nh[q] = packfp2(h0, h1);
            nl[q] = packfp2(v0 - h0, v1 - h1);
        }
        dst[grp * 64 + li]      = make_uint4(nh[0], nh[1], nh[2], nh[3]);
        dst[grp * 64 + li + 32] = make_uint4(nl[0], nl[1], nl[2], nl[3]);
    }
}

// ---------------------------------------------------------------------------
// Project 1x1 GEMM. M=96 x N=128; 4 k-chunks of 48; depth-2 cp.async;
// fp16 single-plane B, fp16 hi/lo A (2 MMAs per fragment).
// x rows 0..60 prefetched into freed smem during last chunk.
// ---------------------------------------------------------------------------
__global__ void __launch_bounds__(256, 2) proj_gemm(const float* __restrict__ x,
                                                    float* __restrict__ out) {
    extern __shared__ uint32_t smu[];
    uint32_t* As0 = smu;                        // PROJ_A_U32
    uint32_t* As1 = smu + PROJ_A_U32;
    uint32_t* Bst = smu + 2 * PROJ_A_U32;       // 2 stages x PROJ_B_U32

    int b = blockIdx.z;
    int p0 = blockIdx.x * 128;
    int tid = threadIdx.x;
    int lane = tid & 31, w = tid >> 5;
    int wr = w >> 2, wc = w & 3;
    int g = lane >> 2, tg = lane & 3;
    const uint32_t* mF = g_mergedF + (size_t)b * 96 * HWP;
    const uint4* Asrc = (const uint4*)(g_WprojSE + (size_t)b * 18432);
    const float* xb = x + (size_t)b * COUTC * HWP;

    auto cp_stage = [&](int c) {
        int stage = c & 1;
        uint32_t dstB = smaddr(Bst) + stage * PROJ_B_U32 * 4;
        const uint4* sF = (const uint4*)(mF + (size_t)(c * 24) * HWP);
        #pragma unroll
        for (int j = 0; j < 3; j++) {
            int v = tid + j * 256;
            int r = v >> 5, c4 = (v & 31);
            int p = p0 + c4 * 4;
            bool ok = p < HWP;                  // zero-fill pad (intended)
            size_t so = (size_t)r * (HWP / 4) + (p0 >> 2) + c4;
            cpa16(dstB + (r * BSS + c4 * 4) * 4, sF + (ok ? so : 0), ok);
        }
        // A chunk: 1152 uint4 = 4*256 + 128 exact
        uint32_t dstA = smaddr(stage ? As1 : As0);
        const uint4* sA = Asrc + c * (PROJ_A_U32 / 4);
        #pragma unroll
        for (int j = 0; j < 4; j++) {
            int v = tid + j * 256;
            cpa16(dstA + v * 16, sA + v, true);
        }
        if (tid < 128) {
            int v = tid + 1024;
            cpa16(dstA + v * 16, sA + v, true);
        }
        cpa_commit();
    };
    cp_stage(0);
    cp_stage(1);

    float acc[3][4][4] = {};

    for (int c = 0; c < 4; c++) {
        uint32_t* Acur = (c & 1) ? As1 : As0;
        uint32_t* BfS = Bst + (c & 1) * PROJ_B_U32;
        cpa_wait<1>();        // chunk c complete (FIFO); c+1 may be in flight
        __syncthreads();

        #pragma unroll
        for (int ki = 0; ki < 3; ki++) {
            uint4 ah[3], al[3];
            #pragma unroll
            for (int mi = 0; mi < 3; mi++) {
                int off = ((wr * 3 + ki) * 3 + mi) * 256 + lane * 4;
                ah[mi] = *(const uint4*)&Acur[off];
                al[mi] = *(const uint4*)&Acur[off + 128];
            }
            uint32_t bf[4][2];
            int kr2 = ki * 8;
            #pragma unroll
            for (int ni = 0; ni < 4; ni++) {
                int nb = wc * 32 + ni * 8 + g;
                bf[ni][0] = BfS[(kr2 + tg) * BSS + nb];
                bf[ni][1] = BfS[(kr2 + tg + 4) * BSS + nb];
            }
            #pragma unroll
            for (int mi = 0; mi < 3; mi++)
                #pragma unroll
                for (int ni = 0; ni < 4; ni++) {
                    mma16f(acc[mi][ni], (const uint32_t*)&ah[mi], bf[ni]);
                    mma16f(acc[mi][ni], (const uint32_t*)&al[mi], bf[ni]);
                }
        }
        __syncthreads();      // buffer (c&1) now free for refill

        if (c < 2) {
            cp_stage(c + 2);
        } else if (c == 2) {
            // Prefetch x rows 0..60 into As0 (36 rows) + Bst stage0 (25 rows)
            #pragma unroll
            for (int j = 0; j < 8; j++) {
                int t = tid + j * 256;
                if (t < 1952) {
                    int row = t >> 5, c4 = t & 31;
                    int p = p0 + c4 * 4;
                    int idx = row * 128 + c4 * 4;               // u32 index
                    uint32_t off = (idx < PROJ_A_U32) ? (uint32_t)idx
                                                      : (uint32_t)(idx + PROJ_A_U32);
                    cpa16(smaddr(smu) + off * 4,
                          xb + (size_t)row * HWP + p, p < HWP);
                }
            }
            cpa_commit();
        }
    }
    cpa_wait<0>();   // x prefetch complete
    __syncthreads();

    float* ob = out + (size_t)b * COUTC * HWP;
    #pragma unroll
    for (int mi = 0; mi < 3; mi++) {
        int o = wr * 48 + mi * 16 + g;
        float b0f = g_bproj[o], b1f = g_bproj[o + 8];
        #pragma unroll
        for (int ni = 0; ni < 4; ni++) {
            int pp = wc * 32 + ni * 8 + tg * 2;
            int p = p0 + pp;
            if (p < HWP) {
                float2 x0, x1;
                {
                    int idx = o * 128 + pp;
                    uint32_t off = (idx < PROJ_A_U32) ? (uint32_t)idx
                                                      : (uint32_t)(idx + PROJ_A_U32);
                    x0 = (o < 61) ? make_float2(__uint_as_float(smu[off]),
                                                __uint_as_float(smu[off + 1]))
                                  : *(const float2*)&xb[(size_t)o * HWP + p];
                }
                {
                    int o2 = o + 8;
                    int idx = o2 * 128 + pp;
                    uint32_t off = (idx < PROJ_A_U32) ? (uint32_t)idx
                                                      : (uint32_t)(idx + PROJ_A_U32);
                    x1 = (o2 < 61) ? make_float2(__uint_as_float(smu[off]),
                                                 __uint_as_float(smu[off + 1]))
                                   : *(const float2*)&xb[(size_t)(o + 8) * HWP + p];
                }
                float2 r0;
                r0.x = silu_f(acc[mi][ni][0] + b0f + x0.x);
                r0.y = silu_f(acc[mi][ni][1] + b0f + x0.y);
                *(float2*)&ob[(size_t)o * HWP + p] = r0;
                float2 r1;
                r1.x = silu_f(acc[mi][ni][2] + b1f + x1.x);
                r1.y = silu_f(acc[mi][ni][3] + b1f + x1.y);
                *(float2*)&ob[(size_t)(o + 8) * HWP + p] = r1;
            }
        }
    }
}

// ---------------------------------------------------------------------------
extern "C" void kernel_launch(void* const* d_in, const int* in_sizes, int n_in,
                              void* d_out, int out_size) {
    const float* x         = (const float*)d_in[0];
    const float* expand_w  = (const float*)d_in[1];
    const float* expand_bn = (const float*)d_in[2];
    const float* dw_w      = (const float*)d_in[3];
    const float* dw_bn     = (const float*)d_in[4];
    const float* id_w      = (const float*)d_in[5];
    const float* id_bn     = (const float*)d_in[6];
    const float* merge_bn  = (const float*)d_in[7];
    const float* se_red_w  = (const float*)d_in[8];
    const float* se_red_b  = (const float*)d_in[9];
    const float* se_exp_w  = (const float*)d_in[10];
    const float* se_exp_b  = (const float*)d_in[11];
    const float* proj_w    = (const float*)d_in[12];
    const float* proj_bn   = (const float*)d_in[13];
    float* out = (float*)d_out;

    cudaFuncSetAttribute(expand_gemm, cudaFuncAttributeMaxDynamicSharedMemorySize, EXP_SMEM);
    cudaFuncSetAttribute(proj_gemm,   cudaFuncAttributeMaxDynamicSharedMemorySize, PROJ_SMEM);

    prep_kernel<<<264, 256>>>(expand_w, expand_bn, dw_w, dw_bn, id_w, id_bn,
                              merge_bn, proj_w, proj_bn);
    expand_gemm<<<dim3(25, 1, BZ), 256, EXP_SMEM>>>(x);
    dwmerge_kernel<<<BZ * 96, 256>>>();
    se_scale_kernel<<<dim3(BZ, 4), 256>>>(se_red_w, se_red_b, se_exp_w, se_exp_b);
    proj_gemm<<<dim3(25, 1, BZ), 256, PROJ_SMEM>>>(x, out);
}

// round 17
// speedup vs baseline: 1.6033x; 1.1249x over previous
#include <cuda_runtime.h>
#include <cuda_bf16.h>
#include <cuda_fp16.h>
#include <math.h>
#include <stdint.h>

#define BZ    64
#define CINC  96
#define COUTC 96
#define MIDC  192
#define HWP   3136
#define EPSBN 1e-5f

#define BSS 136                    // pair-row stride (u32): bank = 8*tg+g, conflict-free
#define EXP_A_U32   3072           // per-mt A chunk  [wr2][ki6][mi2][lane32][q4] fp16 single
#define PROJ_A_U32  2304           // per-kchunk A    [wr2][ki3][mi3][lane32][q4] fp16 single
#define EXP_B_U32   (48 * BSS)     // single fp16 plane, 48 pair-rows
#define PROJ_B_U32  (24 * BSS)     // single fp16 plane per chunk, 24 pair-rows
#define EXP_SMEM  ((2 * EXP_A_U32 + EXP_B_U32) * 4)          // 50688 B
#define PROJ_SMEM ((2 * PROJ_A_U32 + 2 * PROJ_B_U32) * 4)    // 44544 B

// Scratch (device globals: allowed; no cudaMalloc anywhere)
__device__ __align__(16) __half   g_mid[(size_t)BZ * MIDC * HWP];    // fp16 mid
__device__ __align__(16) uint32_t g_mergedF[(size_t)BZ * 96 * HWP];  // packed fp16 (c,c+1)
__device__ float    g_sums[BZ * MIDC];
__device__ __align__(16) uint32_t g_WexpF[9216];    // fp16 single, fragment order
__device__ __align__(16) uint32_t g_WprojF[18432];  // bf16 hi/lo master, fragment order
__device__ __align__(16) uint32_t g_WprojSE[(size_t)BZ * 9216];  // per-batch SE-scaled fp16
__device__ float    g_bexp[MIDC];
__device__ float    g_W9[MIDC * 9];
__device__ float    g_T[MIDC];
__device__ float    g_bproj[COUTC];

__device__ __forceinline__ float silu_f(float v) { return v / (1.f + __expf(-v)); }

__device__ __forceinline__ uint32_t packbf2(float lo_elem, float hi_elem) {
    __nv_bfloat162 t = __floats2bfloat162_rn(lo_elem, hi_elem);  // .x = low 16 bits
    return *(uint32_t*)&t;
}
__device__ __forceinline__ uint32_t packfp2(float lo_elem, float hi_elem) {
    __half2 t = __floats2half2_rn(lo_elem, hi_elem);             // .x = low 16 bits
    return *(uint32_t*)&t;
}
__device__ __forceinline__ float2 unpackbf2(uint32_t u) {
    __nv_bfloat162 t = *(__nv_bfloat162*)&u;
    return __bfloat1622float2(t);
}
__device__ __forceinline__ float bf16hi(float v) {
    return __bfloat162float(__float2bfloat16_rn(v));
}

__device__ __forceinline__ void mma16f(float* c, const uint32_t* a, const uint32_t* b) {
    asm volatile(
        "mma.sync.aligned.m16n8k16.row.col.f32.f16.f16.f32 "
        "{%0,%1,%2,%3},{%4,%5,%6,%7},{%8,%9},{%0,%1,%2,%3};"
        : "+f"(c[0]), "+f"(c[1]), "+f"(c[2]), "+f"(c[3])
        : "r"(a[0]), "r"(a[1]), "r"(a[2]), "r"(a[3]), "r"(b[0]), "r"(b[1]));
}

__device__ __forceinline__ uint32_t smaddr(const void* p) {
    return (uint32_t)__cvta_generic_to_shared(p);
}
__device__ __forceinline__ void cpa16(uint32_t dst_s, const void* src, bool valid) {
    // NOTE: valid=false still WRITES 16 zero bytes to dst (zero-fill).
    int sz = valid ? 16 : 0;
    asm volatile("cp.async.cg.shared.global [%0], [%1], 16, %2;\n"
                 :: "r"(dst_s), "l"(src), "r"(sz));
}
__device__ __forceinline__ void cpa_commit() {
    asm volatile("cp.async.commit_group;\n");
}
template <int N>
__device__ __forceinline__ void cpa_wait() {
    asm volatile("cp.async.wait_group %0;\n" :: "n"(N));
}

// ---------------------------------------------------------------------------
// prep: fold BN; expand weights -> single fp16 fragment order;
// proj weights -> bf16 hi/lo master (fp32-reconstructable for SE scaling).
// ---------------------------------------------------------------------------
__global__ void prep_kernel(const float* __restrict__ expand_w,
                            const float* __restrict__ expand_bn,
                            const float* __restrict__ dw_w,
                            const float* __restrict__ dw_bn,
                            const float* __restrict__ id_w,
                            const float* __restrict__ id_bn,
                            const float* __restrict__ merge_bn,
                            const float* __restrict__ proj_w,
                            const float* __restrict__ proj_bn) {
    int tid = blockIdx.x * blockDim.x + threadIdx.x;
    int nth = gridDim.x * blockDim.x;

    for (int idx = tid; idx < 9216; idx += nth) {
        int q = idx & 3, lane = (idx >> 2) & 31;
        int t = idx >> 7;
        int mi = t & 1; t >>= 1;
        int ki = t % 6; t /= 6;
        int wr = t & 1; t >>= 1;
        int mt = t;
        int m = mt * 64 + wr * 32 + mi * 16 + (lane >> 2) + 8 * (q & 1);
        int k = ki * 16 + (lane & 3) * 2 + 8 * (q >> 1);
        float sc = expand_bn[m] * rsqrtf(expand_bn[3 * MIDC + m] + EPSBN);
        float w0 = expand_w[m * CINC + k] * sc;
        float w1 = expand_w[m * CINC + k + 1] * sc;
        g_WexpF[idx] = packfp2(w0, w1);
    }
    for (int idx = tid; idx < 18432; idx += nth) {
        int q = idx & 3, lane = (idx >> 2) & 31, hl = (idx >> 7) & 1;
        int t = idx >> 8;
        int mi = t % 3; t /= 3;
        int ki = t % 3; t /= 3;
        int wr = t & 1; int chunk = t >> 1;
        int m = wr * 48 + mi * 16 + (lane >> 2) + 8 * (q & 1);
        int k = chunk * 48 + ki * 16 + (lane & 3) * 2 + 8 * (q >> 1);
        float sc = proj_bn[m] * rsqrtf(proj_bn[3 * COUTC + m] + EPSBN);
        float w0 = proj_w[m * MIDC + k] * sc;
        float w1 = proj_w[m * MIDC + k + 1] * sc;
        float h0 = bf16hi(w0), h1 = bf16hi(w1);
        g_WprojF[idx] = hl ? packbf2(w0 - h0, w1 - h1) : packbf2(h0, h1);
    }
    for (int o = tid; o < MIDC; o += nth) {
        float sc = expand_bn[o] * rsqrtf(expand_bn[3 * MIDC + o] + EPSBN);
        g_bexp[o] = expand_bn[MIDC + o] - expand_bn[2 * MIDC + o] * sc;
    }
    for (int c = tid; c < MIDC; c += nth) {
        float dsc = dw_bn[c] * rsqrtf(dw_bn[3 * MIDC + c] + EPSBN);
        float dsh = dw_bn[MIDC + c] - dw_bn[2 * MIDC + c] * dsc;
        float isc = id_bn[c] * rsqrtf(id_bn[3 * MIDC + c] + EPSBN);
        float ish = id_bn[MIDC + c] - id_bn[2 * MIDC + c] * isc;
        float msc = merge_bn[c] * rsqrtf(merge_bn[3 * MIDC + c] + EPSBN);
        float msh = merge_bn[MIDC + c] - merge_bn[2 * MIDC + c] * msc;
        #pragma unroll
        for (int k = 0; k < 9; k++) g_W9[c * 9 + k] = msc * dsc * dw_w[c * 9 + k];
        g_W9[c * 9 + 4] += msc * isc * id_w[c];
        g_T[c] = msc * (dsh + ish) + msh;
    }
    for (int o = tid; o < COUTC; o += nth) {
        float sc = proj_bn[o] * rsqrtf(proj_bn[3 * COUTC + o] + EPSBN);
        g_bproj[o] = proj_bn[COUTC + o] - proj_bn[2 * COUTC + o] * sc;
    }
}

// ---------------------------------------------------------------------------
// Expand 1x1 GEMM. 192(Mx3 passes) x 128(N); warp tile 32x32; fp16 mma,
// single-plane A and B (1 MMA per fragment). fp16 output.
// ---------------------------------------------------------------------------
__global__ void __launch_bounds__(256, 2) expand_gemm(const float* __restrict__ x) {
    extern __shared__ uint32_t smu[];
    uint32_t* As0 = smu;                    // EXP_A_U32
    uint32_t* As1 = smu + EXP_A_U32;
    uint32_t* Bf  = smu + 2 * EXP_A_U32;    // EXP_B_U32 (single plane)
    int b = blockIdx.z;
    int p0 = blockIdx.x * 128;
    int tid = threadIdx.x;
    int lane = tid & 31, w = tid >> 5;
    int wr = w >> 2, wc = w & 3;
    int g = lane >> 2, tg = lane & 3;
    const float* xb = x + (size_t)b * CINC * HWP;
    __half* ob = g_mid + (size_t)b * MIDC * HWP;

    // Prefetch A(0) and A(1) upfront (768 uint4 each = 3*256 exact)
    {
        const uint4* src = (const uint4*)g_WexpF;
        #pragma unroll
        for (int j = 0; j < 3; j++)
            cpa16(smaddr(As0) + (tid + j * 256) * 16, src + tid + j * 256, true);
        cpa_commit();
        src += EXP_A_U32 / 4;
        #pragma unroll
        for (int j = 0; j < 3; j++)
            cpa16(smaddr(As1) + (tid + j * 256) * 16, src + tid + j * 256, true);
        cpa_commit();
    }
    // Convert B to single fp16 plane (overlaps both A fetches)
    #pragma unroll
    for (int j = 0; j < 6; j++) {
        int v = tid + j * 256;
        int k2 = v >> 5, c4 = (v & 31) << 2;
        int p = p0 + c4;
        float4 r0 = make_float4(0.f, 0.f, 0.f, 0.f), r1 = r0;
        if (p < HWP) {
            r0 = *(const float4*)&xb[(size_t)(2 * k2) * HWP + p];
            r1 = *(const float4*)&xb[(size_t)(2 * k2 + 1) * HWP + p];
        }
        uint4 t;
        t.x = packfp2(r0.x, r1.x);
        t.y = packfp2(r0.y, r1.y);
        t.z = packfp2(r0.z, r1.z);
        t.w = packfp2(r0.w, r1.w);
        *(uint4*)&Bf[k2 * BSS + c4] = t;
    }

    for (int mt = 0; mt < 3; mt++) {
        uint32_t* Acur = (mt & 1) ? As1 : As0;
        if (mt == 2) { cpa_wait<0>(); } else { cpa_wait<1>(); }
        __syncthreads();   // A(mt) visible; B visible (mt=0); prev buffer free

        float acc[2][4][4] = {};
        #pragma unroll
        for (int ki = 0; ki < 6; ki++) {
            uint4 ah[2];
            #pragma unroll
            for (int mi = 0; mi < 2; mi++) {
                int off = ((wr * 6 + ki) * 2 + mi) * 128 + lane * 4;
                ah[mi] = *(const uint4*)&Acur[off];
            }
            uint32_t bf[4][2];
            int kr2 = ki * 8;
            #pragma unroll
            for (int ni = 0; ni < 4; ni++) {
                int nb = wc * 32 + ni * 8 + g;
                bf[ni][0] = Bf[(kr2 + tg) * BSS + nb];
                bf[ni][1] = Bf[(kr2 + tg + 4) * BSS + nb];
            }
            #pragma unroll
            for (int mi = 0; mi < 2; mi++)
                #pragma unroll
                for (int ni = 0; ni < 4; ni++)
                    mma16f(acc[mi][ni], (const uint32_t*)&ah[mi], bf[ni]);
        }

        int m0 = mt * 64;
        #pragma unroll
        for (int mi = 0; mi < 2; mi++) {
            int o = m0 + wr * 32 + mi * 16 + g;
            float b0f = g_bexp[o], b1f = g_bexp[o + 8];
            #pragma unroll
            for (int ni = 0; ni < 4; ni++) {
                int p = p0 + wc * 32 + ni * 8 + tg * 2;
                if (p < HWP) {
                    *(__half2*)&ob[(size_t)o * HWP + p] =
                        __floats2half2_rn(silu_f(acc[mi][ni][0] + b0f),
                                          silu_f(acc[mi][ni][1] + b0f));
                    *(__half2*)&ob[(size_t)(o + 8) * HWP + p] =
                        __floats2half2_rn(silu_f(acc[mi][ni][2] + b1f),
                                          silu_f(acc[mi][ni][3] + b1f));
                }
            }
        }
        __syncthreads();   // all reads of Acur done before refill
        if (mt == 0) {
            const uint4* src = ((const uint4*)g_WexpF) + 2 * (EXP_A_U32 / 4);
            #pragma unroll
            for (int j = 0; j < 3; j++)
                cpa16(smaddr(As0) + (tid + j * 256) * 16, src + tid + j * 256, true);
            cpa_commit();
        }
    }
}

// ---------------------------------------------------------------------------
// dwmerge v4: border-only zeroing; single packed-fp16 output plane.
// ---------------------------------------------------------------------------
#define SROW 64
__global__ void __launch_bounds__(256) dwmerge_kernel() {
    __shared__ float sps[2][58 * SROW];
    __shared__ float sred[16];
    int bc = blockIdx.x;
    int b = bc / 96, k2 = bc - b * 96;
    int tid = threadIdx.x;

    int oyA[2], oxA[2];
    const __half* planes[2];
    float w9[2][9], T[2];
    #pragma unroll
    for (int ch = 0; ch < 2; ch++) {
        int c = 2 * k2 + ch;
        int cpre = (c & 3) * 48 + (c >> 2);
        int gg = c & 3;
        oyA[ch] = (gg == 0) ? -1 : (gg == 2) ? 1 : 0;
        oxA[ch] = (gg == 1) ? -1 : (gg == 3) ? 1 : 0;
        planes[ch] = g_mid + ((size_t)b * MIDC + cpre) * HWP;
        #pragma unroll
        for (int k = 0; k < 9; k++) w9[ch][k] = g_W9[c * 9 + k];
        T[ch] = g_T[c];
    }

    // Phase A: fill shifted rows + zero never-written borders (disjoint writes)
    for (int t = tid; t < 1624; t += 256) {
        int ch = t >= 812;
        int u = t - ch * 812;
        int r = u / 14, qq = u - r * 14;
        int hp = r - 1, hs = hp + oyA[ch];
        if ((unsigned)hp < 56u && (unsigned)hs < 56u) {
            uint2 v = *(const uint2*)&planes[ch][hs * 56 + qq * 4];
            float2 f01 = __half22float2(*(__half2*)&v.x);
            float2 f23 = __half22float2(*(__half2*)&v.y);
            float* d = &sps[ch][r * SROW + qq * 4 + (5 - oxA[ch])];
            d[0] = f01.x; d[1] = f01.y; d[2] = f23.x; d[3] = f23.y;
        }
    }
    for (int t = tid; t < 2 * 3 * 16; t += 256) {
        int ch = t >= 48;
        int u = t - ch * 48;
        int slot = u >> 4, c4 = (u & 15) << 2;
        int oy = oyA[ch];
        int rr = (slot == 0) ? 0 : (slot == 1) ? 57
                : (oy == -1) ? 1 : (oy == 1) ? 56 : 0;
        *(float4*)&sps[ch][rr * SROW + c4] = make_float4(0.f, 0.f, 0.f, 0.f);
    }
    for (int t = tid; t < 2 * 2 * 58; t += 256) {
        int ch = t >= 116;
        int u = t - ch * 116;
        int which = u >= 58;
        int rr = u - which * 58;
        int ox = oxA[ch];
        int cc = (ox == 0) ? (which ? 61 : 4)
               : (ox == 1) ? (which ? 61 : 60)
                           : (which ? 5 : 4);
        sps[ch][rr * SROW + cc] = 0.f;
    }
    __syncthreads();

    // Pad-cell fix
    if (tid < 116) {
        int ch = tid >= 58;
        int r = tid - ch * 58;
        int ox = oxA[ch];
        if (ox == 1)  sps[ch][r * SROW + 4] = 0.f;
        if (ox == -1) sps[ch][r * SROW + 61] = 0.f;
    }
    __syncthreads();

    uint32_t* oF = g_mergedF + ((size_t)b * 96 + k2) * HWP;
    float ls0 = 0.f, ls1 = 0.f;

    for (int t = tid; t < 784; t += 256) {
        int h = t / 14, q = t - h * 14;
        float a0[4] = {T[0], T[0], T[0], T[0]};
        float a1[4] = {T[1], T[1], T[1], T[1]};
        #pragma unroll
        for (int ch = 0; ch < 2; ch++) {
            float* accp = ch ? a1 : a0;
            #pragma unroll
            for (int dy = 0; dy < 3; dy++) {
                const float* row = &sps[ch][(h + dy) * SROW + q * 4 + 4];
                float4 A = *(const float4*)row;
                float2 Bv = *(const float2*)(row + 4);
                float wA = w9[ch][dy * 3], wB = w9[ch][dy * 3 + 1], wC = w9[ch][dy * 3 + 2];
                accp[0] += wA * A.x + wB * A.y + wC * A.z;
                accp[1] += wA * A.y + wB * A.z + wC * A.w;
                accp[2] += wA * A.z + wB * A.w + wC * Bv.x;
                accp[3] += wA * A.w + wB * Bv.x + wC * Bv.y;
            }
        }
        uint32_t Fw[4];
        #pragma unroll
        for (int i = 0; i < 4; i++) {
            float s0 = silu_f(a0[i]);
            float s1 = silu_f(a1[i]);
            Fw[i] = packfp2(s0, s1);
            ls0 += s0;
            ls1 += s1;
        }
        int o = h * 56 + q * 4;
        *(uint4*)&oF[o] = make_uint4(Fw[0], Fw[1], Fw[2], Fw[3]);
    }

    int wid = tid >> 5, lane = tid & 31;
    #pragma unroll
    for (int o = 16; o > 0; o >>= 1) {
        ls0 += __shfl_down_sync(0xffffffffu, ls0, o);
        ls1 += __shfl_down_sync(0xffffffffu, ls1, o);
    }
    if (lane == 0) { sred[wid] = ls0; sred[8 + wid] = ls1; }
    __syncthreads();
    if (tid < 16) {
        float v = sred[tid];
        #pragma unroll
        for (int o = 4; o > 0; o >>= 1) v += __shfl_down_sync(0xffffu, v, o);
        if (tid == 0) g_sums[b * 192 + 2 * k2] = v;
        if (tid == 8) g_sums[b * 192 + 2 * k2 + 1] = v;
    }
}

// ---------------------------------------------------------------------------
// SE gating + per-batch scaled proj weights -> single fp16 plane.
// ---------------------------------------------------------------------------
__global__ void __launch_bounds__(256) se_scale_kernel(const float* __restrict__ red_w,
                                                       const float* __restrict__ red_b,
                                                       const float* __restrict__ exp_w,
                                                       const float* __restrict__ exp_b) {
    __shared__ float smean[192];
    __shared__ float sredu[24];
    __shared__ float s_se[192];
    int b = blockIdx.x, cc = blockIdx.y;
    int tid = threadIdx.x;

    if (tid < 192) smean[tid] = g_sums[b * 192 + tid] * (1.f / 3136.f);
    __syncthreads();
    if (tid < 24) {
        int gq = tid >> 1;
        float a = red_b[tid];
        #pragma unroll
        for (int i = 0; i < 16; i++) a += red_w[tid * 16 + i] * smean[gq * 16 + i];
        sredu[tid] = fmaxf(a, 0.f);
    }
    __syncthreads();
    if (tid < 192) {
        int gq = tid >> 4;
        float v = exp_w[tid * 2] * sredu[gq * 2] + exp_w[tid * 2 + 1] * sredu[gq * 2 + 1]
                + exp_b[tid];
        s_se[tid] = 1.f / (1.f + __expf(-v));
    }
    __syncthreads();

    uint32_t* dstb = g_WprojSE + (size_t)b * 9216;
    const uint4* src = ((const uint4*)g_WprojF) + cc * (18432 / 4 / 4);  // 1152 uint4 per chunk
    uint4* dst = ((uint4*)dstb) + cc * (PROJ_A_U32 / 4);                 // 576 uint4 per chunk
    for (int i = tid; i < 576; i += 256) {
        int grp = i >> 5, li = i & 31;
        int ki = (grp / 3) % 3;
        uint4 H = src[grp * 64 + li];
        uint4 L = src[grp * 64 + li + 32];
        int k2a = cc * 24 + ki * 8 + (li & 3);
        float se0 = s_se[2 * k2a], se1 = s_se[2 * k2a + 1];
        float se2 = s_se[2 * k2a + 8], se3 = s_se[2 * k2a + 9];
        uint32_t hu[4] = {H.x, H.y, H.z, H.w};
        uint32_t lu[4] = {L.x, L.y, L.z, L.w};
        uint32_t nh[4];
        #pragma unroll
        for (int q = 0; q < 4; q++) {
            float sA = (q < 2) ? se0 : se2;
            float sB = (q < 2) ? se1 : se3;
            float2 hf = unpackbf2(hu[q]);
            float2 lf = unpackbf2(lu[q]);
            float v0 = (hf.x + lf.x) * sA;
            float v1 = (hf.y + lf.y) * sB;
            nh[q] = packfp2(v0, v1);
        }
        dst[grp * 32 + li] = make_uint4(nh[0], nh[1], nh[2], nh[3]);
    }
}

// ---------------------------------------------------------------------------
// Project 1x1 GEMM. M=96 x N=128; 4 k-chunks of 48; depth-2 cp.async;
// single fp16 A and B (1 MMA per fragment).
// x rows 0..42 prefetched into freed smem during last chunk.
// ---------------------------------------------------------------------------
__global__ void __launch_bounds__(256, 2) proj_gemm(const float* __restrict__ x,
                                                    float* __restrict__ out) {
    extern __shared__ uint32_t smu[];
    uint32_t* As0 = smu;                        // PROJ_A_U32
    uint32_t* As1 = smu + PROJ_A_U32;
    uint32_t* Bst = smu + 2 * PROJ_A_U32;       // 2 stages x PROJ_B_U32

    int b = blockIdx.z;
    int p0 = blockIdx.x * 128;
    int tid = threadIdx.x;
    int lane = tid & 31, w = tid >> 5;
    int wr = w >> 2, wc = w & 3;
    int g = lane >> 2, tg = lane & 3;
    const uint32_t* mF = g_mergedF + (size_t)b * 96 * HWP;
    const uint4* Asrc = (const uint4*)(g_WprojSE + (size_t)b * 9216);
    const float* xb = x + (size_t)b * COUTC * HWP;

    auto cp_stage = [&](int c) {
        int stage = c & 1;
        uint32_t dstB = smaddr(Bst) + stage * PROJ_B_U32 * 4;
        const uint4* sF = (const uint4*)(mF + (size_t)(c * 24) * HWP);
        #pragma unroll
        for (int j = 0; j < 3; j++) {
            int v = tid + j * 256;
            int r = v >> 5, c4 = (v & 31);
            int p = p0 + c4 * 4;
            bool ok = p < HWP;                  // zero-fill pad (intended)
            size_t so = (size_t)r * (HWP / 4) + (p0 >> 2) + c4;
            cpa16(dstB + (r * BSS + c4 * 4) * 4, sF + (ok ? so : 0), ok);
        }
        // A chunk: 576 uint4 = 2*256 + 64 exact
        uint32_t dstA = smaddr(stage ? As1 : As0);
        const uint4* sA = Asrc + c * (PROJ_A_U32 / 4);
        #pragma unroll
        for (int j = 0; j < 2; j++) {
            int v = tid + j * 256;
            cpa16(dstA + v * 16, sA + v, true);
        }
        if (tid < 64) {
            int v = tid + 512;
            cpa16(dstA + v * 16, sA + v, true);
        }
        cpa_commit();
    };
    cp_stage(0);
    cp_stage(1);

    float acc[3][4][4] = {};

    for (int c = 0; c < 4; c++) {
        uint32_t* Acur = (c & 1) ? As1 : As0;
        uint32_t* BfS = Bst + (c & 1) * PROJ_B_U32;
        cpa_wait<1>();        // chunk c complete (FIFO); c+1 may be in flight
        __syncthreads();

        #pragma unroll
        for (int ki = 0; ki < 3; ki++) {
            uint4 ah[3];
            #pragma unroll
            for (int mi = 0; mi < 3; mi++) {
                int off = ((wr * 3 + ki) * 3 + mi) * 128 + lane * 4;
                ah[mi] = *(const uint4*)&Acur[off];
            }
            uint32_t bf[4][2];
            int kr2 = ki * 8;
            #pragma unroll
            for (int ni = 0; ni < 4; ni++) {
                int nb = wc * 32 + ni * 8 + g;
                bf[ni][0] = BfS[(kr2 + tg) * BSS + nb];
                bf[ni][1] = BfS[(kr2 + tg + 4) * BSS + nb];
            }
            #pragma unroll
            for (int mi = 0; mi < 3; mi++)
                #pragma unroll
                for (int ni = 0; ni < 4; ni++)
                    mma16f(acc[mi][ni], (const uint32_t*)&ah[mi], bf[ni]);
        }
        __syncthreads();      // buffer (c&1) now free for refill

        if (c < 2) {
            cp_stage(c + 2);
        } else if (c == 2) {
            // Prefetch x rows 0..42 into As0 (18 rows) + Bst stage0 (25 rows):
            // 43 rows * 32 uint4 = 1376 tasks = 5*256 + 96
            #pragma unroll
            for (int j = 0; j < 6; j++) {
                int t = tid + j * 256;
                if (t < 1376) {
                    int row = t >> 5, c4 = t & 31;
                    int p = p0 + c4 * 4;
                    int idx = row * 128 + c4 * 4;               // u32 index
                    uint32_t off = (idx < PROJ_A_U32) ? (uint32_t)idx
                                                      : (uint32_t)(idx + PROJ_A_U32);
                    cpa16(smaddr(smu) + off * 4,
                          xb + (size_t)row * HWP + p, p < HWP);
                }
            }
            cpa_commit();
        }
    }
    cpa_wait<0>();   // x prefetch complete
    __syncthreads();

    float* ob = out + (size_t)b * COUTC * HWP;
    #pragma unroll
    for (int mi = 0; mi < 3; mi++) {
        int o = wr * 48 + mi * 16 + g;
        float b0f = g_bproj[o], b1f = g_bproj[o + 8];
        #pragma unroll
        for (int ni = 0; ni < 4; ni++) {
            int pp = wc * 32 + ni * 8 + tg * 2;
            int p = p0 + pp;
            if (p < HWP) {
                float2 x0, x1;
                {
                    int idx = o * 128 + pp;
                    uint32_t off = (idx < PROJ_A_U32) ? (uint32_t)idx
                                                      : (uint32_t)(idx + PROJ_A_U32);
                    x0 = (o < 43) ? make_float2(__uint_as_float(smu[off]),
                                                __uint_as_float(smu[off + 1]))
                                  : *(const float2*)&xb[(size_t)o * HWP + p];
                }
                {
                    int o2 = o + 8;
                    int idx = o2 * 128 + pp;
                    uint32_t off = (idx < PROJ_A_U32) ? (uint32_t)idx
                                                      : (uint32_t)(idx + PROJ_A_U32);
                    x1 = (o2 < 43) ? make_float2(__uint_as_float(smu[off]),
                                                 __uint_as_float(smu[off + 1]))
                                   : *(const float2*)&xb[(size_t)(o + 8) * HWP + p];
                }
                float2 r0;
                r0.x = silu_f(acc[mi][ni][0] + b0f + x0.x);
                r0.y = silu_f(acc[mi][ni][1] + b0f + x0.y);
                *(float2*)&ob[(size_t)o * HWP + p] = r0;
                float2 r1;
                r1.x = silu_f(acc[mi][ni][2] + b1f + x1.x);
                r1.y = silu_f(acc[mi][ni][3] + b1f + x1.y);
                *(float2*)&ob[(size_t)(o + 8) * HWP + p] = r1;
            }
        }
    }
}

// ---------------------------------------------------------------------------
extern "C" void kernel_launch(void* const* d_in, const int* in_sizes, int n_in,
                              void* d_out, int out_size) {
    const float* x         = (const float*)d_in[0];
    const float* expand_w  = (const float*)d_in[1];
    const float* expand_bn = (const float*)d_in[2];
    const float* dw_w      = (const float*)d_in[3];
    const float* dw_bn     = (const float*)d_in[4];
    const float* id_w      = (const float*)d_in[5];
    const float* id_bn     = (const float*)d_in[6];
    const float* merge_bn  = (const float*)d_in[7];
    const float* se_red_w  = (const float*)d_in[8];
    const float* se_red_b  = (const float*)d_in[9];
    const float* se_exp_w  = (const float*)d_in[10];
    const float* se_exp_b  = (const float*)d_in[11];
    const float* proj_w    = (const float*)d_in[12];
    const float* proj_bn   = (const float*)d_in[13];
    float* out = (float*)d_out;

    cudaFuncSetAttribute(expand_gemm, cudaFuncAttributeMaxDynamicSharedMemorySize, EXP_SMEM);
    cudaFuncSetAttribute(proj_gemm,   cudaFuncAttributeMaxDynamicSharedMemorySize, PROJ_SMEM);

    prep_kernel<<<264, 256>>>(expand_w, expand_bn, dw_w, dw_bn, id_w, id_bn,
                              merge_bn, proj_w, proj_bn);
    expand_gemm<<<dim3(25, 1, BZ), 256, EXP_SMEM>>>(x);
    dwmerge_kernel<<<BZ * 96, 256>>>();
    se_scale_kernel<<<dim3(BZ, 4), 256>>>(se_red_w, se_red_b, se_exp_w, se_exp_b);
    proj_gemm<<<dim3(25, 1, BZ), 256, PROJ_SMEM>>>(x, out);
}